// round 1
// baseline (speedup 1.0000x reference)
#include <cuda_runtime.h>
#include <math.h>

#define Bdim 4
#define Cdim 64
#define Hdim 128
#define Wdim 128
#define HW (Hdim*Wdim)

// Scratch (device globals: allowed; no runtime allocation)
__device__ float g_t1[Bdim*Cdim*HW];      // 1x1 conv out (offset path)
__device__ float g_t2[Bdim*Cdim*HW];      // 1x1 conv out (mask path)
__device__ float g_off[Bdim*18*HW];       // offset maps
__device__ float g_mask[Bdim*9*HW];       // sigmoid mask maps
__device__ float g_pre[Bdim*Cdim*HW];     // pre-groupnorm output
__device__ float g_stats[Bdim*32*2];      // per-(b,group) mean, rstd

// ---------------------------------------------------------------------------
// Kernel 1: two fused 1x1 convs (C->C): t1 = x*w_off1, t2 = x*w_mask1
// Block: 256 thr, 32 pixels, all 64 couts for both convs.
// ---------------------------------------------------------------------------
__global__ __launch_bounds__(256) void k1_pointwise(
    const float* __restrict__ x,
    const float* __restrict__ w1,
    const float* __restrict__ w2)
{
    __shared__ float sx[64*32];
    __shared__ float sw1[64*64];
    __shared__ float sw2[64*64];
    const int tid = threadIdx.x;
    const int b   = blockIdx.y;
    const int p0  = blockIdx.x * 32;

    for (int i = tid; i < 4096; i += 256) { sw1[i] = w1[i]; sw2[i] = w2[i]; }
    const float* xb = x + (size_t)b * Cdim * HW;
    for (int i = tid; i < 64*32; i += 256) {
        int cin = i >> 5, p = i & 31;
        sx[cin*32 + p] = xb[cin*HW + p0 + p];
    }
    __syncthreads();

    const int px  = tid & 31;
    const int grp = tid >> 5;          // 0..7 -> 8 couts each
    const int cb  = grp * 8;
    float a1[8], a2[8];
#pragma unroll
    for (int j = 0; j < 8; j++) { a1[j] = 0.f; a2[j] = 0.f; }

    for (int cin = 0; cin < 64; cin++) {
        float xv = sx[cin*32 + px];
#pragma unroll
        for (int j = 0; j < 8; j++) {
            a1[j] = fmaf(sw1[(cb+j)*64 + cin], xv, a1[j]);
            a2[j] = fmaf(sw2[(cb+j)*64 + cin], xv, a2[j]);
        }
    }
#pragma unroll
    for (int j = 0; j < 8; j++) {
        g_t1[((size_t)b*64 + cb + j)*HW + p0 + px] = a1[j];
        g_t2[((size_t)b*64 + cb + j)*HW + p0 + px] = a2[j];
    }
}

// ---------------------------------------------------------------------------
// Kernel 2: two 3x3 convs, pad=1:  off = conv(t1, w_off2[18,64,3,3])
//                                  mask = sigmoid(conv(t2, w_mask2[9,64,3,3]))
// Block: 256 thr = 16x16 pixel tile; 27 accumulators/thread.
// All weights staged in dynamic SMEM once.
// ---------------------------------------------------------------------------
__global__ __launch_bounds__(256) void k2_conv3x3(
    const float* __restrict__ wo,
    const float* __restrict__ wm)
{
    extern __shared__ float sm[];
    float* swo = sm;              // 18*64*9 = 10368
    float* swm = swo + 10368;     //  9*64*9 =  5184
    float* st1 = swm + 5184;      // 18*19   =   342
    float* st2 = st1 + 342;       // 18*19   =   342

    const int tid = threadIdx.x;
    for (int i = tid; i < 10368; i += 256) swo[i] = wo[i];
    for (int i = tid; i < 5184;  i += 256) swm[i] = wm[i];

    const int b  = blockIdx.z;
    const int y0 = blockIdx.y * 16;
    const int x0 = blockIdx.x * 16;
    const int ty = tid >> 4, tx = tid & 15;

    float acc[27];
#pragma unroll
    for (int o = 0; o < 27; o++) acc[o] = 0.f;

    const float* t1b = g_t1 + (size_t)b * 64 * HW;
    const float* t2b = g_t2 + (size_t)b * 64 * HW;

    for (int cin = 0; cin < 64; cin++) {
        __syncthreads();
        for (int i = tid; i < 324; i += 256) {
            int r = i / 18, c2 = i % 18;
            int yy = y0 + r - 1;
            int xx = x0 + c2 - 1;
            bool ok = (yy >= 0) & (yy < Hdim) & (xx >= 0) & (xx < Wdim);
            float v1 = ok ? t1b[cin*HW + yy*Wdim + xx] : 0.f;
            float v2 = ok ? t2b[cin*HW + yy*Wdim + xx] : 0.f;
            st1[r*19 + c2] = v1;
            st2[r*19 + c2] = v2;
        }
        __syncthreads();

        float r1[9], r2[9];
#pragma unroll
        for (int t = 0; t < 9; t++) {
            int dy = t / 3, dxx = t % 3;
            r1[t] = st1[(ty+dy)*19 + tx + dxx];
            r2[t] = st2[(ty+dy)*19 + tx + dxx];
        }
        const float* w  = swo + cin*9;   // [o][cin][t]: o*576 + t
        const float* w2 = swm + cin*9;
#pragma unroll
        for (int o = 0; o < 18; o++)
#pragma unroll
            for (int t = 0; t < 9; t++)
                acc[o] = fmaf(w[o*576 + t], r1[t], acc[o]);
#pragma unroll
        for (int o = 0; o < 9; o++)
#pragma unroll
            for (int t = 0; t < 9; t++)
                acc[18+o] = fmaf(w2[o*576 + t], r2[t], acc[18+o]);
    }

    const int pix = (y0+ty)*Wdim + x0 + tx;
#pragma unroll
    for (int o = 0; o < 18; o++)
        g_off[((size_t)b*18 + o)*HW + pix] = acc[o];
#pragma unroll
    for (int o = 0; o < 9; o++)
        g_mask[((size_t)b*9 + o)*HW + pix] = 1.f / (1.f + expf(-acc[18+o]));
}

// ---------------------------------------------------------------------------
// Kernel 3: deformable bilinear gather + mask*weight einsum + bias.
// Block: 256 thr = 2 rows x 128 cols of one batch.
// Per-pixel tap coefficients (validity+mask folded) precomputed in registers,
// reused across all 64 channels.
// ---------------------------------------------------------------------------
__global__ __launch_bounds__(256) void k3_sample(
    const float* __restrict__ x,
    const float* __restrict__ wgt,   // [64][9]
    const float* __restrict__ bias)
{
    __shared__ float sw[64*9];
    __shared__ float sb[64];
    const int tid = threadIdx.x;
    for (int i = tid; i < 576; i += 256) sw[i] = wgt[i];
    if (tid < 64) sb[tid] = bias[tid];

    const int b  = blockIdx.y;
    const int gy = blockIdx.x * 2 + (tid >> 7);
    const int gx = tid & 127;
    const int pix = gy*Wdim + gx;

    const float* offb = g_off  + (size_t)b * 18 * HW;
    const float* mkb  = g_mask + (size_t)b * 9  * HW;

    int   i00[9], dxx[9], dyW[9];
    float ay0[9], ay1[9], ax0[9], ax1[9];
#pragma unroll
    for (int k = 0; k < 9; k++) {
        float oy = offb[(2*k  )*HW + pix];
        float ox = offb[(2*k+1)*HW + pix];
        float mk = mkb [ k     *HW + pix];
        float py  = oy + (float)gy + (float)(k/3 - 1);
        float pxx = ox + (float)gx + (float)(k%3 - 1);
        float y0f = floorf(py),  x0f = floorf(pxx);
        float wy1 = py - y0f,    wx1 = pxx - x0f;
        int   y0  = (int)y0f,    xx0 = (int)x0f;
        int cy0 = min(max(y0,   0), Hdim-1), cy1 = min(max(y0+1, 0), Hdim-1);
        int cx0 = min(max(xx0,  0), Wdim-1), cx1 = min(max(xx0+1,0), Wdim-1);
        i00[k] = cy0*Wdim + cx0;
        dxx[k] = cx1 - cx0;
        dyW[k] = (cy1 - cy0)*Wdim;
        float vy0 = (y0   >= 0 && y0   < Hdim) ? 1.f : 0.f;
        float vy1 = (y0+1 >= 0 && y0+1 < Hdim) ? 1.f : 0.f;
        float vx0 = (xx0  >= 0 && xx0  < Wdim) ? 1.f : 0.f;
        float vx1 = (xx0+1>= 0 && xx0+1< Wdim) ? 1.f : 0.f;
        ay0[k] = (1.f - wy1) * vy0 * mk;
        ay1[k] = wy1 * vy1 * mk;
        ax0[k] = (1.f - wx1) * vx0;
        ax1[k] = wx1 * vx1;
    }
    __syncthreads();

    const float* xb = x + (size_t)b * 64 * HW;
    for (int c = 0; c < 64; c++) {
        const float* xc = xb + c*HW;
        float acc = 0.f;
#pragma unroll
        for (int k = 0; k < 9; k++) {
            float v00 = __ldg(xc + i00[k]);
            float v01 = __ldg(xc + i00[k] + dxx[k]);
            float v10 = __ldg(xc + i00[k] + dyW[k]);
            float v11 = __ldg(xc + i00[k] + dyW[k] + dxx[k]);
            float s = ay0[k]*fmaf(ax1[k], v01, ax0[k]*v00)
                    + ay1[k]*fmaf(ax1[k], v11, ax0[k]*v10);
            acc = fmaf(sw[c*9 + k], s, acc);
        }
        g_pre[((size_t)b*64 + c)*HW + pix] = acc + sb[c];
    }
}

// ---------------------------------------------------------------------------
// Kernel 4a: group stats (mean, rstd) per (b, group). 2 channels/group are
// contiguous in memory -> 32768 contiguous floats. Deterministic tree reduce.
// ---------------------------------------------------------------------------
__global__ __launch_bounds__(256) void k4a_stats()
{
    __shared__ float ss[256], ss2[256];
    const int bg = blockIdx.x;            // 0..127
    const int b = bg >> 5, g = bg & 31;
    const float* p = g_pre + ((size_t)b*64 + g*2) * HW;
    float s = 0.f, s2 = 0.f;
    for (int i = threadIdx.x; i < 2*HW; i += 256) {
        float v = p[i];
        s += v;
        s2 = fmaf(v, v, s2);
    }
    ss [threadIdx.x] = s;
    ss2[threadIdx.x] = s2;
    __syncthreads();
    for (int st = 128; st > 0; st >>= 1) {
        if (threadIdx.x < st) {
            ss [threadIdx.x] += ss [threadIdx.x + st];
            ss2[threadIdx.x] += ss2[threadIdx.x + st];
        }
        __syncthreads();
    }
    if (threadIdx.x == 0) {
        float mean = ss[0] * (1.f/32768.f);
        float var  = ss2[0] * (1.f/32768.f) - mean*mean;
        g_stats[bg*2]   = mean;
        g_stats[bg*2+1] = rsqrtf(var + 1e-5f);
    }
}

// ---------------------------------------------------------------------------
// Kernel 4b: normalize + gamma/beta + exact GELU -> output
// ---------------------------------------------------------------------------
__global__ __launch_bounds__(256) void k4b_norm(
    const float* __restrict__ gamma,
    const float* __restrict__ beta,
    float* __restrict__ out)
{
    const int i = blockIdx.x * 256 + threadIdx.x;   // 4.19M total
    const int c = (i >> 14) & 63;                   // HW = 2^14
    const int b = i >> 20;                          // 64*HW = 2^20
    const int bg = b*32 + (c >> 1);
    float mean = g_stats[bg*2];
    float rstd = g_stats[bg*2 + 1];
    float v = g_pre[i];
    float y = (v - mean) * rstd * __ldg(gamma + c) + __ldg(beta + c);
    out[i] = 0.5f * y * (1.f + erff(y * 0.70710678118654752f));
}

// ---------------------------------------------------------------------------
extern "C" void kernel_launch(void* const* d_in, const int* in_sizes, int n_in,
                              void* d_out, int out_size)
{
    const float* x       = (const float*)d_in[0];
    const float* w_off1  = (const float*)d_in[1];
    const float* w_off2  = (const float*)d_in[2];
    const float* w_mask1 = (const float*)d_in[3];
    const float* w_mask2 = (const float*)d_in[4];
    const float* weight  = (const float*)d_in[5];
    const float* bias    = (const float*)d_in[6];
    const float* gamma   = (const float*)d_in[7];
    const float* beta    = (const float*)d_in[8];
    float* out = (float*)d_out;

    // k2 needs 64944 B dynamic smem (>48KB default)
    cudaFuncSetAttribute(k2_conv3x3, cudaFuncAttributeMaxDynamicSharedMemorySize, 65536);

    k1_pointwise<<<dim3(HW/32, Bdim), 256>>>(x, w_off1, w_mask1);
    k2_conv3x3 <<<dim3(8, 8, Bdim), 256, 64944>>>(w_off2, w_mask2);
    k3_sample  <<<dim3(Hdim/2, Bdim), 256>>>(x, weight, bias);
    k4a_stats  <<<128, 256>>>();
    k4b_norm   <<<(Bdim*Cdim*HW)/256, 256>>>(gamma, beta, out);
}

// round 4
// speedup vs baseline: 2.1822x; 2.1822x over previous
#include <cuda_runtime.h>
#include <cuda_fp16.h>
#include <mma.h>
#include <math.h>
#include <stdint.h>

using namespace nvcuda;

#define Bdim 4
#define Cdim 64
#define Hdim 128
#define Wdim 128
#define HW (Hdim*Wdim)

#define PADH 72            // halfs per smem row (144 B: 16B bank shift per row)

// ---------------------------------------------------------------------------
// Device scratch
// ---------------------------------------------------------------------------
__device__ uint4 t1Th[Bdim*HW*8];       // half [pix][64ch] (offset path)
__device__ uint4 t2Th[Bdim*HW*8];       // half [pix][64ch] (mask path)
__device__ uint4 wB1h[1024];            // half [128 cout][64 cin]  (w_off1 | w_mask1)
__device__ uint4 wB2o[2304];            // half [9 tap][32 cout][64 cin] (w_off2, rows 18-31 zero)
__device__ uint4 wB2m[2304];            // half [9 tap][32 cout][64 cin] (w_mask2, rows 9-31 zero)
__device__ float g_off [Bdim*18*HW];
__device__ float g_mask[Bdim*9*HW];
__device__ float g_pre [Bdim*Cdim*HW];
__device__ float2 g_part[128*8];
__device__ float g_stats[256];

// ---------------------------------------------------------------------------
// Kernel 0: weight prep -> half, GEMM-friendly layouts
// ---------------------------------------------------------------------------
__global__ __launch_bounds__(256) void k0_prep(
    const float* __restrict__ w_off1, const float* __restrict__ w_mask1,
    const float* __restrict__ w_off2, const float* __restrict__ w_mask2)
{
    __half* b1  = (__half*)wB1h;
    __half* b2o = (__half*)wB2o;
    __half* b2m = (__half*)wB2m;
    for (int j = blockIdx.x * 256 + threadIdx.x; j < 45056; j += gridDim.x * 256) {
        if (j < 8192) {
            int o = j >> 6, c = j & 63;
            float v = (o < 64) ? w_off1[o*64 + c] : w_mask1[(o-64)*64 + c];
            b1[j] = __float2half_rn(v);
        } else if (j < 26624) {
            int j2 = j - 8192;
            int t = j2 >> 11, o = (j2 >> 6) & 31, c = j2 & 63;
            float v = (o < 18) ? w_off2[o*576 + c*9 + t] : 0.f;
            b2o[j2] = __float2half_rn(v);
        } else {
            int j2 = j - 26624;
            int t = j2 >> 11, o = (j2 >> 6) & 31, c = j2 & 63;
            float v = (o < 9) ? w_mask2[o*576 + c*9 + t] : 0.f;
            b2m[j2] = __float2half_rn(v);
        }
    }
}

// ---------------------------------------------------------------------------
// Kernel 1: both 1x1 convs as one wmma GEMM.
// D[128 pix, 128 cout] = A[128 pix, 64 cin] x W[128 cout, 64 cin]^T
// Outputs re-packed pixel-major half into t1Th (couts 0-63) / t2Th (64-127).
// ---------------------------------------------------------------------------
#define K1_A    0
#define K1_B    18432                  // 128*144
#define K1_STG  36864                  // + 128*144
#define K1_SMEM (36864 + 128*132*4)    // staging [128][132] f32 -> 104448 B

__global__ __launch_bounds__(256) void k1_wmma(const float* __restrict__ x)
{
    extern __shared__ char sm[];
    __half* Ah = (__half*)(sm + K1_A);
    __half* Bh = (__half*)(sm + K1_B);
    float*  Sg = (float*) (sm + K1_STG);
    const int tid = threadIdx.x;
    const int wid = tid >> 5, lid = tid & 31;
    const int p0  = blockIdx.x * 128;       // global pixel (incl batch)
    const int b   = p0 >> 14;
    const int pi  = p0 & 16383;

    // B: weights [128 cout][64 cin] -> smem rows of 144B
    for (int j = tid; j < 1024; j += 256) {
        int o = j >> 3, seg = j & 7;
        *(uint4*)((char*)Bh + o*144 + seg*16) = wB1h[j];
    }
    // A: transpose x[c][p] -> [p][c] half2
    const float* xb = x + (size_t)b * 64 * HW + pi;
    for (int j = tid; j < 4096; j += 256) {
        int cp = j >> 7, p = j & 127;
        float va = xb[(2*cp  )*HW + p];
        float vb = xb[(2*cp+1)*HW + p];
        __half2 h = __floats2half2_rn(va, vb);
        *(uint32_t*)((char*)Ah + p*144 + cp*4) = *(uint32_t*)&h;
    }
    __syncthreads();

    wmma::fragment<wmma::accumulator, 16, 16, 16, float> acc[8];
#pragma unroll
    for (int n = 0; n < 8; n++) wmma::fill_fragment(acc[n], 0.f);
    for (int k = 0; k < 4; k++) {
        wmma::fragment<wmma::matrix_a, 16, 16, 16, __half, wmma::row_major> fa;
        wmma::load_matrix_sync(fa, Ah + wid*16*PADH + k*16, PADH);
#pragma unroll
        for (int n = 0; n < 8; n++) {
            wmma::fragment<wmma::matrix_b, 16, 16, 16, __half, wmma::col_major> fb;
            wmma::load_matrix_sync(fb, Bh + n*16*PADH + k*16, PADH);
            wmma::mma_sync(acc[n], fa, fb, acc[n]);
        }
    }
    // stage f32 per-warp strip, then pack half -> global
    float* st = Sg + wid*16*132;
#pragma unroll
    for (int n = 0; n < 8; n++)
        wmma::store_matrix_sync(st + n*16, acc[n], 132, wmma::mem_row_major);
    __syncwarp();
#pragma unroll
    for (int i = 0; i < 8; i++) {
        int item  = i*32 + lid;
        int row   = item >> 4;
        int chunk = item & 15;              // 8 couts each
        const float* s = st + row*132 + chunk*8;
        uint4 o4;
        __half2 h;
        h = __floats2half2_rn(s[0], s[1]); o4.x = *(uint32_t*)&h;
        h = __floats2half2_rn(s[2], s[3]); o4.y = *(uint32_t*)&h;
        h = __floats2half2_rn(s[4], s[5]); o4.z = *(uint32_t*)&h;
        h = __floats2half2_rn(s[6], s[7]); o4.w = *(uint32_t*)&h;
        int gp = p0 + wid*16 + row;
        if (chunk < 8) t1Th[(size_t)gp*8 + chunk]     = o4;
        else           t2Th[(size_t)gp*8 + (chunk-8)] = o4;
    }
}

// ---------------------------------------------------------------------------
// Kernel 2: 3x3 convs as im2col GEMM (tap-major K = 9 atoms of 64 ch).
// blockIdx.y: 0 = offset path (t1Th x wB2o -> g_off), 1 = mask path.
// One block = one image row (128 pixels).
// f32 staging is OVERLAID on the A-tile region (sync separates phases).
// ---------------------------------------------------------------------------
#define K2_ASECT 18432                 // 128*144 per tap
#define K2_A     0
#define K2_B     (9*18432)             // 165888
#define K2_BSECT 4608                  // 32*144 per tap
#define K2_SMEM  (K2_B + 9*4608)       // 207360 B total

__global__ __launch_bounds__(256) void k2_wmma()
{
    extern __shared__ char sm[];
    __half* Ah = (__half*)(sm + K2_A);
    __half* Bh = (__half*)(sm + K2_B);
    float*  Sg = (float*) (sm + K2_A);   // overlay: reused after MMA phase
    const int tid = threadIdx.x;
    const int wid = tid >> 5, lid = tid & 31;
    const int bx = blockIdx.x;
    const int b = bx >> 7, y = bx & 127;
    const int path = blockIdx.y;

    // B weights: [9][32][8 uint4]
    const uint4* wsrc = path ? wB2m : wB2o;
    for (int j = tid; j < 2304; j += 256) {
        int t = j >> 8, o = (j >> 3) & 31, seg = j & 7;
        *(uint4*)((char*)Bh + t*K2_BSECT + o*144 + seg*16) = wsrc[j];
    }
    // A im2col: (tap, pixel, 16B seg)
    const uint4* src = path ? t2Th : t1Th;
    const uint4 z4 = make_uint4(0u,0u,0u,0u);
    for (int j = tid; j < 9216; j += 256) {
        int t = j >> 10, p = (j >> 3) & 127, seg = j & 7;
        int yy = y + t/3 - 1, xx = p + t%3 - 1;
        uint4 v = z4;
        if ((unsigned)yy < 128u && (unsigned)xx < 128u)
            v = src[(size_t)((b << 14) + (yy << 7) + xx) * 8 + seg];
        *(uint4*)((char*)Ah + t*K2_ASECT + p*144 + seg*16) = v;
    }
    __syncthreads();

    wmma::fragment<wmma::accumulator, 16, 16, 16, float> acc[2];
    wmma::fill_fragment(acc[0], 0.f);
    wmma::fill_fragment(acc[1], 0.f);
    for (int t = 0; t < 9; t++) {
        const __half* At = Ah + t*(K2_ASECT/2) + wid*16*PADH;
        const __half* Bt = Bh + t*(K2_BSECT/2);
#pragma unroll
        for (int k = 0; k < 4; k++) {
            wmma::fragment<wmma::matrix_a, 16, 16, 16, __half, wmma::row_major> fa;
            wmma::load_matrix_sync(fa, At + k*16, PADH);
#pragma unroll
            for (int n = 0; n < 2; n++) {
                wmma::fragment<wmma::matrix_b, 16, 16, 16, __half, wmma::col_major> fb;
                wmma::load_matrix_sync(fb, Bt + n*16*PADH + k*16, PADH);
                wmma::mma_sync(acc[n], fa, fb, acc[n]);
            }
        }
    }
    __syncthreads();   // all A reads done before staging overlay writes

    float* st = Sg + wid*16*36;
    wmma::store_matrix_sync(st,      acc[0], 36, wmma::mem_row_major);
    wmma::store_matrix_sync(st + 16, acc[1], 36, wmma::mem_row_major);
    __syncwarp();

    const int p_ = lid & 15;                 // pixel within warp strip
    const int oh = lid >> 4;                 // 0/1: which half of outputs
    const int pix = y*Wdim + wid*16 + p_;
    if (path == 0) {
#pragma unroll
        for (int j = 0; j < 9; j++) {
            int o = oh*9 + j;
            g_off[((size_t)b*18 + o)*HW + pix] = st[p_*36 + o];
        }
    } else if (oh == 0) {
#pragma unroll
        for (int j = 0; j < 9; j++) {
            float v = st[p_*36 + j];
            g_mask[((size_t)b*9 + j)*HW + pix] = 1.f / (1.f + expf(-v));
        }
    }
}

// ---------------------------------------------------------------------------
// Kernel 3: deformable bilinear gather + mask*weight einsum + bias (fp32)
// ---------------------------------------------------------------------------
__global__ __launch_bounds__(256) void k3_sample(
    const float* __restrict__ x,
    const float* __restrict__ wgt,
    const float* __restrict__ bias)
{
    __shared__ float sw[64*9];
    __shared__ float sb[64];
    const int tid = threadIdx.x;
    for (int i = tid; i < 576; i += 256) sw[i] = wgt[i];
    if (tid < 64) sb[tid] = bias[tid];

    const int b  = blockIdx.y;
    const int gy = blockIdx.x * 2 + (tid >> 7);
    const int gx = tid & 127;
    const int pix = gy*Wdim + gx;

    const float* offb = g_off  + (size_t)b * 18 * HW;
    const float* mkb  = g_mask + (size_t)b * 9  * HW;

    int   i00[9], dxx[9], dyW[9];
    float c00[9], c01[9], c10[9], c11[9];
#pragma unroll
    for (int k = 0; k < 9; k++) {
        float oy = offb[(2*k  )*HW + pix];
        float ox = offb[(2*k+1)*HW + pix];
        float mk = mkb [ k     *HW + pix];
        float py  = oy + (float)gy + (float)(k/3 - 1);
        float pxx = ox + (float)gx + (float)(k%3 - 1);
        float y0f = floorf(py),  x0f = floorf(pxx);
        float wy1 = py - y0f,    wx1 = pxx - x0f;
        int   y0  = (int)y0f,    xx0 = (int)x0f;
        int cy0 = min(max(y0,   0), Hdim-1), cy1 = min(max(y0+1, 0), Hdim-1);
        int cx0 = min(max(xx0,  0), Wdim-1), cx1 = min(max(xx0+1,0), Wdim-1);
        i00[k] = cy0*Wdim + cx0;
        dxx[k] = cx1 - cx0;
        dyW[k] = (cy1 - cy0)*Wdim;
        float vy0 = (y0   >= 0 && y0   < Hdim) ? 1.f : 0.f;
        float vy1 = (y0+1 >= 0 && y0+1 < Hdim) ? 1.f : 0.f;
        float vx0 = (xx0  >= 0 && xx0  < Wdim) ? 1.f : 0.f;
        float vx1 = (xx0+1>= 0 && xx0+1< Wdim) ? 1.f : 0.f;
        float ay0 = (1.f - wy1) * vy0 * mk;
        float ay1 = wy1 * vy1 * mk;
        float ax0 = (1.f - wx1) * vx0;
        float ax1 = wx1 * vx1;
        c00[k] = ay0*ax0; c01[k] = ay0*ax1;
        c10[k] = ay1*ax0; c11[k] = ay1*ax1;
    }
    __syncthreads();

    const float* xb = x + (size_t)b * 64 * HW;
    for (int c = 0; c < 64; c++) {
        const float* xc = xb + c*HW;
        float acc = 0.f;
#pragma unroll
        for (int k = 0; k < 9; k++) {
            float v00 = __ldg(xc + i00[k]);
            float v01 = __ldg(xc + i00[k] + dxx[k]);
            float v10 = __ldg(xc + i00[k] + dyW[k]);
            float v11 = __ldg(xc + i00[k] + dyW[k] + dxx[k]);
            float s = c00[k]*v00;
            s = fmaf(c01[k], v01, s);
            s = fmaf(c10[k], v10, s);
            s = fmaf(c11[k], v11, s);
            acc = fmaf(sw[c*9 + k], s, acc);
        }
        g_pre[((size_t)b*64 + c)*HW + pix] = acc + sb[c];
    }
}

// ---------------------------------------------------------------------------
// Kernel 4a: group stats via 1024-block partials + tiny final pass
// ---------------------------------------------------------------------------
__global__ __launch_bounds__(256) void k4a1_partial()
{
    const int bi = blockIdx.x;          // bg*8 + chunk
    const int bg = bi >> 3, ch = bi & 7;
    const float4* p = (const float4*)(g_pre + (size_t)bg*32768 + ch*4096);
    float s = 0.f, s2 = 0.f;
    for (int j = threadIdx.x; j < 1024; j += 256) {
        float4 v = p[j];
        s += v.x + v.y + v.z + v.w;
        s2 = fmaf(v.x, v.x, s2); s2 = fmaf(v.y, v.y, s2);
        s2 = fmaf(v.z, v.z, s2); s2 = fmaf(v.w, v.w, s2);
    }
#pragma unroll
    for (int o = 16; o > 0; o >>= 1) {
        s  += __shfl_xor_sync(0xFFFFFFFF, s,  o);
        s2 += __shfl_xor_sync(0xFFFFFFFF, s2, o);
    }
    __shared__ float2 sp[8];
    if ((threadIdx.x & 31) == 0) sp[threadIdx.x >> 5] = make_float2(s, s2);
    __syncthreads();
    if (threadIdx.x == 0) {
        float ts = 0.f, ts2 = 0.f;
#pragma unroll
        for (int w = 0; w < 8; w++) { ts += sp[w].x; ts2 += sp[w].y; }
        g_part[bi] = make_float2(ts, ts2);
    }
}

__global__ __launch_bounds__(128) void k4a2_final()
{
    const int bg = threadIdx.x;          // 0..127
    float s = 0.f, s2 = 0.f;
#pragma unroll
    for (int i = 0; i < 8; i++) {
        float2 v = g_part[bg*8 + i];
        s += v.x; s2 += v.y;
    }
    float mean = s * (1.f/32768.f);
    float var  = s2 * (1.f/32768.f) - mean*mean;
    g_stats[bg*2]   = mean;
    g_stats[bg*2+1] = rsqrtf(var + 1e-5f);
}

// ---------------------------------------------------------------------------
// Kernel 4b: normalize + affine + exact GELU (float4)
// ---------------------------------------------------------------------------
__global__ __launch_bounds__(256) void k4b_norm(
    const float* __restrict__ gamma,
    const float* __restrict__ beta,
    float* __restrict__ out)
{
    const int i4 = blockIdx.x * 256 + threadIdx.x;
    const int i  = i4 << 2;
    const int c  = (i >> 14) & 63;
    const int b  = i >> 20;
    const int bg = b*32 + (c >> 1);
    const float mean = g_stats[bg*2];
    const float rstd = g_stats[bg*2 + 1];
    const float ga = __ldg(gamma + c), be = __ldg(beta + c);
    float4 v = ((const float4*)g_pre)[i4];
    float4 r;
    float yv;
    yv = (v.x - mean) * rstd * ga + be;
    r.x = 0.5f * yv * (1.f + erff(yv * 0.70710678118654752f));
    yv = (v.y - mean) * rstd * ga + be;
    r.y = 0.5f * yv * (1.f + erff(yv * 0.70710678118654752f));
    yv = (v.z - mean) * rstd * ga + be;
    r.z = 0.5f * yv * (1.f + erff(yv * 0.70710678118654752f));
    yv = (v.w - mean) * rstd * ga + be;
    r.w = 0.5f * yv * (1.f + erff(yv * 0.70710678118654752f));
    ((float4*)out)[i4] = r;
}

// ---------------------------------------------------------------------------
extern "C" void kernel_launch(void* const* d_in, const int* in_sizes, int n_in,
                              void* d_out, int out_size)
{
    const float* x       = (const float*)d_in[0];
    const float* w_off1  = (const float*)d_in[1];
    const float* w_off2  = (const float*)d_in[2];
    const float* w_mask1 = (const float*)d_in[3];
    const float* w_mask2 = (const float*)d_in[4];
    const float* weight  = (const float*)d_in[5];
    const float* bias    = (const float*)d_in[6];
    const float* gamma   = (const float*)d_in[7];
    const float* beta    = (const float*)d_in[8];
    float* out = (float*)d_out;

    cudaFuncSetAttribute(k1_wmma, cudaFuncAttributeMaxDynamicSharedMemorySize, K1_SMEM);
    cudaFuncSetAttribute(k2_wmma, cudaFuncAttributeMaxDynamicSharedMemorySize, K2_SMEM);

    k0_prep <<<64, 256>>>(w_off1, w_mask1, w_off2, w_mask2);
    k1_wmma <<<512, 256, K1_SMEM>>>(x);
    k2_wmma <<<dim3(512, 2), 256, K2_SMEM>>>();
    k3_sample<<<dim3(Hdim/2, Bdim), 256>>>(x, weight, bias);
    k4a1_partial<<<1024, 256>>>();
    k4a2_final<<<1, 128>>>();
    k4b_norm<<<4096, 256>>>(gamma, beta, out);
}

// round 5
// speedup vs baseline: 2.3024x; 1.0551x over previous
#include <cuda_runtime.h>
#include <cuda_fp16.h>
#include <mma.h>
#include <math.h>
#include <stdint.h>

using namespace nvcuda;

#define Bdim 4
#define Cdim 64
#define Hdim 128
#define Wdim 128
#define HW (Hdim*Wdim)

#define PADH 72            // halfs per smem row (144 B: 16B bank shift per row)

// ---------------------------------------------------------------------------
// Device scratch
// ---------------------------------------------------------------------------
__device__ uint4 t1Th[Bdim*HW*8];       // half [pix][64ch] (offset path)
__device__ uint4 t2Th[Bdim*HW*8];       // half [pix][64ch] (mask path)
__device__ uint4 wB1h[1024];            // half [128 cout][64 cin]  (w_off1 | w_mask1)
__device__ uint4 wB2o[2304];            // half [9 tap][32 cout][64 cin] (w_off2, rows 18-31 zero)
__device__ uint4 wB2m[2304];            // half [9 tap][32 cout][64 cin] (w_mask2, rows 9-31 zero)
__device__ float g_off [Bdim*18*HW];
__device__ float g_mask[Bdim*9*HW];
__device__ float g_pre [Bdim*Cdim*HW];
__device__ float2 g_part[2048*32];      // per-block per-group partial (sum, sumsq)
__device__ float g_stats[256];

// ---------------------------------------------------------------------------
// Kernel 0: weight prep -> half, GEMM-friendly layouts
// ---------------------------------------------------------------------------
__global__ __launch_bounds__(256) void k0_prep(
    const float* __restrict__ w_off1, const float* __restrict__ w_mask1,
    const float* __restrict__ w_off2, const float* __restrict__ w_mask2)
{
    __half* b1  = (__half*)wB1h;
    __half* b2o = (__half*)wB2o;
    __half* b2m = (__half*)wB2m;
    for (int j = blockIdx.x * 256 + threadIdx.x; j < 45056; j += gridDim.x * 256) {
        if (j < 8192) {
            int o = j >> 6, c = j & 63;
            float v = (o < 64) ? w_off1[o*64 + c] : w_mask1[(o-64)*64 + c];
            b1[j] = __float2half_rn(v);
        } else if (j < 26624) {
            int j2 = j - 8192;
            int t = j2 >> 11, o = (j2 >> 6) & 31, c = j2 & 63;
            float v = (o < 18) ? w_off2[o*576 + c*9 + t] : 0.f;
            b2o[j2] = __float2half_rn(v);
        } else {
            int j2 = j - 26624;
            int t = j2 >> 11, o = (j2 >> 6) & 31, c = j2 & 63;
            float v = (o < 9) ? w_mask2[o*576 + c*9 + t] : 0.f;
            b2m[j2] = __float2half_rn(v);
        }
    }
}

// ---------------------------------------------------------------------------
// Kernel 1: both 1x1 convs as one wmma GEMM.
// ---------------------------------------------------------------------------
#define K1_A    0
#define K1_B    18432                  // 128*144
#define K1_STG  36864
#define K1_SMEM (36864 + 128*132*4)    // 104448 B

__global__ __launch_bounds__(256) void k1_wmma(const float* __restrict__ x)
{
    extern __shared__ char sm[];
    __half* Ah = (__half*)(sm + K1_A);
    __half* Bh = (__half*)(sm + K1_B);
    float*  Sg = (float*) (sm + K1_STG);
    const int tid = threadIdx.x;
    const int wid = tid >> 5, lid = tid & 31;
    const int p0  = blockIdx.x * 128;
    const int b   = p0 >> 14;
    const int pi  = p0 & 16383;

    for (int j = tid; j < 1024; j += 256) {
        int o = j >> 3, seg = j & 7;
        *(uint4*)((char*)Bh + o*144 + seg*16) = wB1h[j];
    }
    const float* xb = x + (size_t)b * 64 * HW + pi;
    for (int j = tid; j < 4096; j += 256) {
        int cp = j >> 7, p = j & 127;
        float va = xb[(2*cp  )*HW + p];
        float vb = xb[(2*cp+1)*HW + p];
        __half2 h = __floats2half2_rn(va, vb);
        *(uint32_t*)((char*)Ah + p*144 + cp*4) = *(uint32_t*)&h;
    }
    __syncthreads();

    wmma::fragment<wmma::accumulator, 16, 16, 16, float> acc[8];
#pragma unroll
    for (int n = 0; n < 8; n++) wmma::fill_fragment(acc[n], 0.f);
    for (int k = 0; k < 4; k++) {
        wmma::fragment<wmma::matrix_a, 16, 16, 16, __half, wmma::row_major> fa;
        wmma::load_matrix_sync(fa, Ah + wid*16*PADH + k*16, PADH);
#pragma unroll
        for (int n = 0; n < 8; n++) {
            wmma::fragment<wmma::matrix_b, 16, 16, 16, __half, wmma::col_major> fb;
            wmma::load_matrix_sync(fb, Bh + n*16*PADH + k*16, PADH);
            wmma::mma_sync(acc[n], fa, fb, acc[n]);
        }
    }
    float* st = Sg + wid*16*132;
#pragma unroll
    for (int n = 0; n < 8; n++)
        wmma::store_matrix_sync(st + n*16, acc[n], 132, wmma::mem_row_major);
    __syncwarp();
#pragma unroll
    for (int i = 0; i < 8; i++) {
        int item  = i*32 + lid;
        int row   = item >> 4;
        int chunk = item & 15;
        const float* s = st + row*132 + chunk*8;
        uint4 o4;
        __half2 h;
        h = __floats2half2_rn(s[0], s[1]); o4.x = *(uint32_t*)&h;
        h = __floats2half2_rn(s[2], s[3]); o4.y = *(uint32_t*)&h;
        h = __floats2half2_rn(s[4], s[5]); o4.z = *(uint32_t*)&h;
        h = __floats2half2_rn(s[6], s[7]); o4.w = *(uint32_t*)&h;
        int gp = p0 + wid*16 + row;
        if (chunk < 8) t1Th[(size_t)gp*8 + chunk]     = o4;
        else           t2Th[(size_t)gp*8 + (chunk-8)] = o4;
    }
}

// ---------------------------------------------------------------------------
// Kernel 2: 3x3 convs as im2col GEMM (tap-major K = 9 atoms of 64 ch).
// ---------------------------------------------------------------------------
#define K2_ASECT 18432
#define K2_A     0
#define K2_B     (9*18432)
#define K2_BSECT 4608
#define K2_SMEM  (K2_B + 9*4608)       // 207360 B

__global__ __launch_bounds__(256) void k2_wmma()
{
    extern __shared__ char sm[];
    __half* Ah = (__half*)(sm + K2_A);
    __half* Bh = (__half*)(sm + K2_B);
    float*  Sg = (float*) (sm + K2_A);   // overlay after MMA phase
    const int tid = threadIdx.x;
    const int wid = tid >> 5, lid = tid & 31;
    const int bx = blockIdx.x;
    const int b = bx >> 7, y = bx & 127;
    const int path = blockIdx.y;

    const uint4* wsrc = path ? wB2m : wB2o;
    for (int j = tid; j < 2304; j += 256) {
        int t = j >> 8, o = (j >> 3) & 31, seg = j & 7;
        *(uint4*)((char*)Bh + t*K2_BSECT + o*144 + seg*16) = wsrc[j];
    }
    const uint4* src = path ? t2Th : t1Th;
    const uint4 z4 = make_uint4(0u,0u,0u,0u);
    for (int j = tid; j < 9216; j += 256) {
        int t = j >> 10, p = (j >> 3) & 127, seg = j & 7;
        int yy = y + t/3 - 1, xx = p + t%3 - 1;
        uint4 v = z4;
        if ((unsigned)yy < 128u && (unsigned)xx < 128u)
            v = src[(size_t)((b << 14) + (yy << 7) + xx) * 8 + seg];
        *(uint4*)((char*)Ah + t*K2_ASECT + p*144 + seg*16) = v;
    }
    __syncthreads();

    wmma::fragment<wmma::accumulator, 16, 16, 16, float> acc[2];
    wmma::fill_fragment(acc[0], 0.f);
    wmma::fill_fragment(acc[1], 0.f);
    for (int t = 0; t < 9; t++) {
        const __half* At = Ah + t*(K2_ASECT/2) + wid*16*PADH;
        const __half* Bt = Bh + t*(K2_BSECT/2);
#pragma unroll
        for (int k = 0; k < 4; k++) {
            wmma::fragment<wmma::matrix_a, 16, 16, 16, __half, wmma::row_major> fa;
            wmma::load_matrix_sync(fa, At + k*16, PADH);
#pragma unroll
            for (int n = 0; n < 2; n++) {
                wmma::fragment<wmma::matrix_b, 16, 16, 16, __half, wmma::col_major> fb;
                wmma::load_matrix_sync(fb, Bt + n*16*PADH + k*16, PADH);
                wmma::mma_sync(acc[n], fa, fb, acc[n]);
            }
        }
    }
    __syncthreads();

    float* st = Sg + wid*16*36;
    wmma::store_matrix_sync(st,      acc[0], 36, wmma::mem_row_major);
    wmma::store_matrix_sync(st + 16, acc[1], 36, wmma::mem_row_major);
    __syncwarp();

    const int p_ = lid & 15;
    const int oh = lid >> 4;
    const int pix = y*Wdim + wid*16 + p_;
    if (path == 0) {
#pragma unroll
        for (int j = 0; j < 9; j++) {
            int o = oh*9 + j;
            g_off[((size_t)b*18 + o)*HW + pix] = st[p_*36 + o];
        }
    } else if (oh == 0) {
#pragma unroll
        for (int j = 0; j < 9; j++) {
            float v = st[p_*36 + j];
            g_mask[((size_t)b*9 + j)*HW + pix] = 1.f / (1.f + expf(-v));
        }
    }
}

// ---------------------------------------------------------------------------
// Kernel 3: deformable gather + einsum + bias, FUSED groupnorm partials.
// Block = 32 pixels x 512 threads (16 channel-groups of 4 channels).
// Phase 1: 288 threads build 32x9 tap records in smem.
// Phase 2: per-thread 4-channel gather loop, low regs, high MLP.
// Epilogue: warp-shuffle partial (sum,sumsq) per group -> g_part[block][group].
// ---------------------------------------------------------------------------
__global__ __launch_bounds__(512) void k3_sample(
    const float* __restrict__ x,
    const float* __restrict__ wgt,
    const float* __restrict__ bias)
{
    __shared__ float  sw[64*9];
    __shared__ float  sb[64];
    __shared__ int4   sI[9*32];
    __shared__ float4 sC[9*32];

    const int tid = threadIdx.x;
    for (int i = tid; i < 576; i += 512) sw[i] = wgt[i];
    if (tid < 64) sb[tid] = bias[tid];

    const int blk = blockIdx.x;             // 2048
    const int b   = blk >> 9;               // 512 blocks per batch
    const int p0  = (blk & 511) * 32;       // pixel within image

    if (tid < 288) {
        const int k = tid >> 5;             // 0..8
        const int p = tid & 31;
        const int pix = p0 + p;
        const int gy = pix >> 7, gx = pix & 127;
        const float* offb = g_off  + (size_t)b * 18 * HW;
        const float* mkb  = g_mask + (size_t)b * 9  * HW;
        float oy = offb[(2*k  )*HW + pix];
        float ox = offb[(2*k+1)*HW + pix];
        float mk = mkb [ k     *HW + pix];
        float py  = oy + (float)gy + (float)(k/3 - 1);
        float pxx = ox + (float)gx + (float)(k%3 - 1);
        float y0f = floorf(py),  x0f = floorf(pxx);
        float wy1 = py - y0f,    wx1 = pxx - x0f;
        int   y0  = (int)y0f,    xx0 = (int)x0f;
        int cy0 = min(max(y0,   0), Hdim-1), cy1 = min(max(y0+1, 0), Hdim-1);
        int cx0 = min(max(xx0,  0), Wdim-1), cx1 = min(max(xx0+1,0), Wdim-1);
        float vy0 = (y0   >= 0 && y0   < Hdim) ? 1.f : 0.f;
        float vy1 = (y0+1 >= 0 && y0+1 < Hdim) ? 1.f : 0.f;
        float vx0 = (xx0  >= 0 && xx0  < Wdim) ? 1.f : 0.f;
        float vx1 = (xx0+1>= 0 && xx0+1< Wdim) ? 1.f : 0.f;
        float ay0 = (1.f - wy1) * vy0 * mk;
        float ay1 = wy1 * vy1 * mk;
        float ax0 = (1.f - wx1) * vx0;
        float ax1 = wx1 * vx1;
        sI[k*32 + p] = make_int4(cy0*Wdim + cx0, cx1 - cx0, (cy1 - cy0)*Wdim, 0);
        sC[k*32 + p] = make_float4(ay0*ax0, ay0*ax1, ay1*ax0, ay1*ax1);
    }
    __syncthreads();

    const int p   = tid & 31;
    const int cg  = tid >> 5;               // 0..15 -> channels cg*4..cg*4+3
    const int pix = p0 + p;
    const float* xb = x + (size_t)b * 64 * HW;

    float acc[4] = {0.f, 0.f, 0.f, 0.f};
    for (int k = 0; k < 9; k++) {
        int4   I = sI[k*32 + p];
        float4 C = sC[k*32 + p];
#pragma unroll
        for (int c8 = 0; c8 < 4; c8++) {
            const float* xc = xb + (cg*4 + c8)*HW;
            float v00 = __ldg(xc + I.x);
            float v01 = __ldg(xc + I.x + I.y);
            float v10 = __ldg(xc + I.x + I.z);
            float v11 = __ldg(xc + I.x + I.z + I.y);
            float s = C.x*v00;
            s = fmaf(C.y, v01, s);
            s = fmaf(C.z, v10, s);
            s = fmaf(C.w, v11, s);
            acc[c8] = fmaf(sw[(cg*4 + c8)*9 + k], s, acc[c8]);
        }
    }

    // write + groupnorm partials (channels 4cg..4cg+3 = groups 2cg, 2cg+1)
    float s0 = 0.f, q0 = 0.f, s1 = 0.f, q1 = 0.f;
#pragma unroll
    for (int c8 = 0; c8 < 4; c8++) {
        int c = cg*4 + c8;
        float v = acc[c8] + sb[c];
        g_pre[((size_t)b*64 + c)*HW + pix] = v;
        if (c8 < 2) { s0 += v; q0 = fmaf(v, v, q0); }
        else        { s1 += v; q1 = fmaf(v, v, q1); }
    }
#pragma unroll
    for (int o = 16; o > 0; o >>= 1) {
        s0 += __shfl_xor_sync(0xFFFFFFFF, s0, o);
        q0 += __shfl_xor_sync(0xFFFFFFFF, q0, o);
        s1 += __shfl_xor_sync(0xFFFFFFFF, s1, o);
        q1 += __shfl_xor_sync(0xFFFFFFFF, q1, o);
    }
    if ((tid & 31) == 0) {
        g_part[(size_t)blk*32 + 2*cg    ] = make_float2(s0, q0);
        g_part[(size_t)blk*32 + 2*cg + 1] = make_float2(s1, q1);
    }
}

// ---------------------------------------------------------------------------
// Kernel 4a: final stats: reduce 512 block-partials per (b,group).
// ---------------------------------------------------------------------------
__global__ __launch_bounds__(256) void k4a_final()
{
    __shared__ float2 sp[256];
    const int bg = blockIdx.x;              // 0..127
    const int b = bg >> 5, g = bg & 31;
    float s = 0.f, q = 0.f;
    for (int j = threadIdx.x; j < 512; j += 256) {
        float2 v = g_part[(size_t)(b*512 + j)*32 + g];
        s += v.x; q += v.y;
    }
    sp[threadIdx.x] = make_float2(s, q);
    __syncthreads();
    for (int st = 128; st > 0; st >>= 1) {
        if (threadIdx.x < st) {
            sp[threadIdx.x].x += sp[threadIdx.x + st].x;
            sp[threadIdx.x].y += sp[threadIdx.x + st].y;
        }
        __syncthreads();
    }
    if (threadIdx.x == 0) {
        float mean = sp[0].x * (1.f/32768.f);
        float var  = sp[0].y * (1.f/32768.f) - mean*mean;
        g_stats[bg*2]   = mean;
        g_stats[bg*2+1] = rsqrtf(var + 1e-5f);
    }
}

// ---------------------------------------------------------------------------
// Kernel 4b: normalize + affine + exact GELU (float4)
// ---------------------------------------------------------------------------
__global__ __launch_bounds__(256) void k4b_norm(
    const float* __restrict__ gamma,
    const float* __restrict__ beta,
    float* __restrict__ out)
{
    const int i4 = blockIdx.x * 256 + threadIdx.x;
    const int i  = i4 << 2;
    const int c  = (i >> 14) & 63;
    const int b  = i >> 20;
    const int bg = b*32 + (c >> 1);
    const float mean = g_stats[bg*2];
    const float rstd = g_stats[bg*2 + 1];
    const float ga = __ldg(gamma + c), be = __ldg(beta + c);
    float4 v = ((const float4*)g_pre)[i4];
    float4 r;
    float yv;
    yv = (v.x - mean) * rstd * ga + be;
    r.x = 0.5f * yv * (1.f + erff(yv * 0.70710678118654752f));
    yv = (v.y - mean) * rstd * ga + be;
    r.y = 0.5f * yv * (1.f + erff(yv * 0.70710678118654752f));
    yv = (v.z - mean) * rstd * ga + be;
    r.z = 0.5f * yv * (1.f + erff(yv * 0.70710678118654752f));
    yv = (v.w - mean) * rstd * ga + be;
    r.w = 0.5f * yv * (1.f + erff(yv * 0.70710678118654752f));
    ((float4*)out)[i4] = r;
}

// ---------------------------------------------------------------------------
extern "C" void kernel_launch(void* const* d_in, const int* in_sizes, int n_in,
                              void* d_out, int out_size)
{
    const float* x       = (const float*)d_in[0];
    const float* w_off1  = (const float*)d_in[1];
    const float* w_off2  = (const float*)d_in[2];
    const float* w_mask1 = (const float*)d_in[3];
    const float* w_mask2 = (const float*)d_in[4];
    const float* weight  = (const float*)d_in[5];
    const float* bias    = (const float*)d_in[6];
    const float* gamma   = (const float*)d_in[7];
    const float* beta    = (const float*)d_in[8];
    float* out = (float*)d_out;

    cudaFuncSetAttribute(k1_wmma, cudaFuncAttributeMaxDynamicSharedMemorySize, K1_SMEM);
    cudaFuncSetAttribute(k2_wmma, cudaFuncAttributeMaxDynamicSharedMemorySize, K2_SMEM);

    k0_prep <<<64, 256>>>(w_off1, w_mask1, w_off2, w_mask2);
    k1_wmma <<<512, 256, K1_SMEM>>>(x);
    k2_wmma <<<dim3(512, 2), 256, K2_SMEM>>>();
    k3_sample<<<2048, 512>>>(x, weight, bias);
    k4a_final<<<128, 256>>>();
    k4b_norm<<<4096, 256>>>(gamma, beta, out);
}

// round 7
// speedup vs baseline: 2.5502x; 1.1076x over previous
#include <cuda_runtime.h>
#include <cuda_fp16.h>
#include <mma.h>
#include <math.h>
#include <stdint.h>

using namespace nvcuda;

#define Bdim 4
#define Cdim 64
#define Hdim 128
#define Wdim 128
#define HW (Hdim*Wdim)

#define PADH 72            // halfs per smem row (144 B: 16B bank shift per row)

// ---------------------------------------------------------------------------
// Device scratch
// ---------------------------------------------------------------------------
__device__ uint4 t1Th[Bdim*HW*8];       // half [pix][64ch] (offset path)
__device__ uint4 t2Th[Bdim*HW*8];       // half [pix][64ch] (mask path)
__device__ uint2 g_xq[Bdim*16*HW];      // half x, channel-quad packed: [b][c4][pix]
__device__ uint4 wB1h[1024];            // half [128 cout][64 cin]  (w_off1 | w_mask1)
__device__ uint4 wB2o[2304];            // half [9 tap][32 cout][64 cin] (w_off2, rows 18-31 zero)
__device__ uint4 wB2m[2304];            // half [9 tap][32 cout][64 cin] (w_mask2, rows 9-31 zero)
__device__ float g_off [Bdim*18*HW];
__device__ float g_mask[Bdim*9*HW];
__device__ float g_pre [Bdim*Cdim*HW];
__device__ float2 g_part[2048*32];      // per-block per-group partial (sum, sumsq)
__device__ float g_stats[256];

// ---------------------------------------------------------------------------
// Kernel 0: weight prep -> half, GEMM-friendly layouts
// ---------------------------------------------------------------------------
__global__ __launch_bounds__(256) void k0_prep(
    const float* __restrict__ w_off1, const float* __restrict__ w_mask1,
    const float* __restrict__ w_off2, const float* __restrict__ w_mask2)
{
    __half* b1  = (__half*)wB1h;
    __half* b2o = (__half*)wB2o;
    __half* b2m = (__half*)wB2m;
    for (int j = blockIdx.x * 256 + threadIdx.x; j < 45056; j += gridDim.x * 256) {
        if (j < 8192) {
            int o = j >> 6, c = j & 63;
            float v = (o < 64) ? w_off1[o*64 + c] : w_mask1[(o-64)*64 + c];
            b1[j] = __float2half_rn(v);
        } else if (j < 26624) {
            int j2 = j - 8192;
            int t = j2 >> 11, o = (j2 >> 6) & 31, c = j2 & 63;
            float v = (o < 18) ? w_off2[o*576 + c*9 + t] : 0.f;
            b2o[j2] = __float2half_rn(v);
        } else {
            int j2 = j - 26624;
            int t = j2 >> 11, o = (j2 >> 6) & 31, c = j2 & 63;
            float v = (o < 9) ? w_mask2[o*576 + c*9 + t] : 0.f;
            b2m[j2] = __float2half_rn(v);
        }
    }
}

// ---------------------------------------------------------------------------
// Kernel 1: both 1x1 convs as one wmma GEMM; also emits g_xq (quad-packed x).
// ---------------------------------------------------------------------------
#define K1_A    0
#define K1_B    18432                  // 128*144
#define K1_STG  36864
#define K1_SMEM (36864 + 128*132*4)    // 104448 B

__global__ __launch_bounds__(256) void k1_wmma(const float* __restrict__ x)
{
    extern __shared__ char sm[];
    __half* Ah = (__half*)(sm + K1_A);
    __half* Bh = (__half*)(sm + K1_B);
    float*  Sg = (float*) (sm + K1_STG);
    const int tid = threadIdx.x;
    const int wid = tid >> 5, lid = tid & 31;
    const int p0  = blockIdx.x * 128;
    const int b   = p0 >> 14;
    const int pi  = p0 & 16383;

    for (int j = tid; j < 1024; j += 256) {
        int o = j >> 3, seg = j & 7;
        *(uint4*)((char*)Bh + o*144 + seg*16) = wB1h[j];
    }
    const float* xb = x + (size_t)b * 64 * HW + pi;
    for (int j = tid; j < 4096; j += 256) {
        int cp = j >> 7, p = j & 127;
        float va = xb[(2*cp  )*HW + p];
        float vb = xb[(2*cp+1)*HW + p];
        __half2 h = __floats2half2_rn(va, vb);
        *(uint32_t*)((char*)Ah + p*144 + cp*4) = *(uint32_t*)&h;
    }
    __syncthreads();

    // emit quad-packed x gather table: g_xq[(b*16+c4)*HW + pix]
    for (int j = tid; j < 2048; j += 256) {
        int c4 = j >> 7, p = j & 127;
        uint2 v = *(uint2*)((char*)Ah + p*144 + c4*8);
        g_xq[(size_t)((b*16 + c4) << 14) + pi + p] = v;
    }

    wmma::fragment<wmma::accumulator, 16, 16, 16, float> acc[8];
#pragma unroll
    for (int n = 0; n < 8; n++) wmma::fill_fragment(acc[n], 0.f);
    for (int k = 0; k < 4; k++) {
        wmma::fragment<wmma::matrix_a, 16, 16, 16, __half, wmma::row_major> fa;
        wmma::load_matrix_sync(fa, Ah + wid*16*PADH + k*16, PADH);
#pragma unroll
        for (int n = 0; n < 8; n++) {
            wmma::fragment<wmma::matrix_b, 16, 16, 16, __half, wmma::col_major> fb;
            wmma::load_matrix_sync(fb, Bh + n*16*PADH + k*16, PADH);
            wmma::mma_sync(acc[n], fa, fb, acc[n]);
        }
    }
    float* st = Sg + wid*16*132;
#pragma unroll
    for (int n = 0; n < 8; n++)
        wmma::store_matrix_sync(st + n*16, acc[n], 132, wmma::mem_row_major);
    __syncwarp();
#pragma unroll
    for (int i = 0; i < 8; i++) {
        int item  = i*32 + lid;
        int row   = item >> 4;
        int chunk = item & 15;
        const float* s = st + row*132 + chunk*8;
        uint4 o4;
        __half2 h;
        h = __floats2half2_rn(s[0], s[1]); o4.x = *(uint32_t*)&h;
        h = __floats2half2_rn(s[2], s[3]); o4.y = *(uint32_t*)&h;
        h = __floats2half2_rn(s[4], s[5]); o4.z = *(uint32_t*)&h;
        h = __floats2half2_rn(s[6], s[7]); o4.w = *(uint32_t*)&h;
        int gp = p0 + wid*16 + row;
        if (chunk < 8) t1Th[(size_t)gp*8 + chunk]     = o4;
        else           t2Th[(size_t)gp*8 + (chunk-8)] = o4;
    }
}

// ---------------------------------------------------------------------------
// Kernel 2: 3x3 convs as im2col GEMM (tap-major K = 9 atoms of 64 ch).
// ---------------------------------------------------------------------------
#define K2_ASECT 18432
#define K2_A     0
#define K2_B     (9*18432)
#define K2_BSECT 4608
#define K2_SMEM  (K2_B + 9*4608)       // 207360 B

__global__ __launch_bounds__(256) void k2_wmma()
{
    extern __shared__ char sm[];
    __half* Ah = (__half*)(sm + K2_A);
    __half* Bh = (__half*)(sm + K2_B);
    float*  Sg = (float*) (sm + K2_A);   // overlay after MMA phase
    const int tid = threadIdx.x;
    const int wid = tid >> 5, lid = tid & 31;
    const int bx = blockIdx.x;
    const int b = bx >> 7, y = bx & 127;
    const int path = blockIdx.y;

    const uint4* wsrc = path ? wB2m : wB2o;
    for (int j = tid; j < 2304; j += 256) {
        int t = j >> 8, o = (j >> 3) & 31, seg = j & 7;
        *(uint4*)((char*)Bh + t*K2_BSECT + o*144 + seg*16) = wsrc[j];
    }
    const uint4* src = path ? t2Th : t1Th;
    const uint4 z4 = make_uint4(0u,0u,0u,0u);
    for (int j = tid; j < 9216; j += 256) {
        int t = j >> 10, p = (j >> 3) & 127, seg = j & 7;
        int yy = y + t/3 - 1, xx = p + t%3 - 1;
        uint4 v = z4;
        if ((unsigned)yy < 128u && (unsigned)xx < 128u)
            v = src[(size_t)((b << 14) + (yy << 7) + xx) * 8 + seg];
        *(uint4*)((char*)Ah + t*K2_ASECT + p*144 + seg*16) = v;
    }
    __syncthreads();

    wmma::fragment<wmma::accumulator, 16, 16, 16, float> acc[2];
    wmma::fill_fragment(acc[0], 0.f);
    wmma::fill_fragment(acc[1], 0.f);
    for (int t = 0; t < 9; t++) {
        const __half* At = Ah + t*(K2_ASECT/2) + wid*16*PADH;
        const __half* Bt = Bh + t*(K2_BSECT/2);
#pragma unroll
        for (int k = 0; k < 4; k++) {
            wmma::fragment<wmma::matrix_a, 16, 16, 16, __half, wmma::row_major> fa;
            wmma::load_matrix_sync(fa, At + k*16, PADH);
#pragma unroll
            for (int n = 0; n < 2; n++) {
                wmma::fragment<wmma::matrix_b, 16, 16, 16, __half, wmma::col_major> fb;
                wmma::load_matrix_sync(fb, Bt + n*16*PADH + k*16, PADH);
                wmma::mma_sync(acc[n], fa, fb, acc[n]);
            }
        }
    }
    __syncthreads();

    float* st = Sg + wid*16*36;
    wmma::store_matrix_sync(st,      acc[0], 36, wmma::mem_row_major);
    wmma::store_matrix_sync(st + 16, acc[1], 36, wmma::mem_row_major);
    __syncwarp();

    const int p_ = lid & 15;
    const int oh = lid >> 4;
    const int pix = y*Wdim + wid*16 + p_;
    if (path == 0) {
#pragma unroll
        for (int j = 0; j < 9; j++) {
            int o = oh*9 + j;
            g_off[((size_t)b*18 + o)*HW + pix] = st[p_*36 + o];
        }
    } else if (oh == 0) {
#pragma unroll
        for (int j = 0; j < 9; j++) {
            float v = st[p_*36 + j];
            g_mask[((size_t)b*9 + j)*HW + pix] = 1.f / (1.f + expf(-v));
        }
    }
}

// ---------------------------------------------------------------------------
// Kernel 3: deformable gather (half quad-packed) + einsum + bias,
// fused groupnorm partials. Block = 32 pixels x 512 threads.
// ---------------------------------------------------------------------------
__global__ __launch_bounds__(512) void k3_sample(
    const float* __restrict__ wgt,
    const float* __restrict__ bias)
{
    __shared__ float4 sw4[9*16];        // [k][cg] weight quad
    __shared__ float  sb[64];
    __shared__ int4   sI[9*32];
    __shared__ float4 sC[9*32];

    const int tid = threadIdx.x;
    if (tid < 144) {
        int k = tid >> 4, cg = tid & 15;
        sw4[k*16 + cg] = make_float4(wgt[(cg*4  )*9 + k], wgt[(cg*4+1)*9 + k],
                                     wgt[(cg*4+2)*9 + k], wgt[(cg*4+3)*9 + k]);
    }
    if (tid >= 448) sb[tid - 448] = bias[tid - 448];

    const int blk = blockIdx.x;             // 2048
    const int b   = blk >> 9;               // 512 blocks per batch
    const int p0  = (blk & 511) * 32;       // pixel within image

    if (tid < 288) {
        const int k = tid >> 5;             // 0..8
        const int p = tid & 31;
        const int pix = p0 + p;
        const int gy = pix >> 7, gx = pix & 127;
        const float* offb = g_off  + (size_t)b * 18 * HW;
        const float* mkb  = g_mask + (size_t)b * 9  * HW;
        float oy = offb[(2*k  )*HW + pix];
        float ox = offb[(2*k+1)*HW + pix];
        float mk = mkb [ k     *HW + pix];
        float py  = oy + (float)gy + (float)(k/3 - 1);
        float pxx = ox + (float)gx + (float)(k%3 - 1);
        float y0f = floorf(py),  x0f = floorf(pxx);
        float wy1 = py - y0f,    wx1 = pxx - x0f;
        int   y0  = (int)y0f,    xx0 = (int)x0f;
        int cy0 = min(max(y0,   0), Hdim-1), cy1 = min(max(y0+1, 0), Hdim-1);
        int cx0 = min(max(xx0,  0), Wdim-1), cx1 = min(max(xx0+1,0), Wdim-1);
        float vy0 = (y0   >= 0 && y0   < Hdim) ? 1.f : 0.f;
        float vy1 = (y0+1 >= 0 && y0+1 < Hdim) ? 1.f : 0.f;
        float vx0 = (xx0  >= 0 && xx0  < Wdim) ? 1.f : 0.f;
        float vx1 = (xx0+1>= 0 && xx0+1< Wdim) ? 1.f : 0.f;
        float ay0 = (1.f - wy1) * vy0 * mk;
        float ay1 = wy1 * vy1 * mk;
        float ax0 = (1.f - wx1) * vx0;
        float ax1 = wx1 * vx1;
        sI[k*32 + p] = make_int4(cy0*Wdim + cx0, cx1 - cx0, (cy1 - cy0)*Wdim, 0);
        sC[k*32 + p] = make_float4(ay0*ax0, ay0*ax1, ay1*ax0, ay1*ax1);
    }
    __syncthreads();

    const int p   = tid & 31;
    const int cg  = tid >> 5;               // 0..15 -> channels cg*4..cg*4+3
    const int pix = p0 + p;
    const uint2* xq = g_xq + (size_t)((b*16 + cg) << 14);

    float a0 = 0.f, a1 = 0.f, a2 = 0.f, a3 = 0.f;
    for (int k = 0; k < 9; k++) {
        int4   I  = sI[k*32 + p];
        float4 C  = sC[k*32 + p];
        float4 W  = sw4[k*16 + cg];
        uint2 u00 = __ldg(xq + I.x);
        uint2 u01 = __ldg(xq + I.x + I.y);
        uint2 u10 = __ldg(xq + I.x + I.z);
        uint2 u11 = __ldg(xq + I.x + I.z + I.y);
        float2 fa00 = __half22float2(*(__half2*)&u00.x), fb00 = __half22float2(*(__half2*)&u00.y);
        float2 fa01 = __half22float2(*(__half2*)&u01.x), fb01 = __half22float2(*(__half2*)&u01.y);
        float2 fa10 = __half22float2(*(__half2*)&u10.x), fb10 = __half22float2(*(__half2*)&u10.y);
        float2 fa11 = __half22float2(*(__half2*)&u11.x), fb11 = __half22float2(*(__half2*)&u11.y);
        float s0 = C.x*fa00.x; s0 = fmaf(C.y, fa01.x, s0); s0 = fmaf(C.z, fa10.x, s0); s0 = fmaf(C.w, fa11.x, s0);
        float s1 = C.x*fa00.y; s1 = fmaf(C.y, fa01.y, s1); s1 = fmaf(C.z, fa10.y, s1); s1 = fmaf(C.w, fa11.y, s1);
        float s2 = C.x*fb00.x; s2 = fmaf(C.y, fb01.x, s2); s2 = fmaf(C.z, fb10.x, s2); s2 = fmaf(C.w, fb11.x, s2);
        float s3 = C.x*fb00.y; s3 = fmaf(C.y, fb01.y, s3); s3 = fmaf(C.z, fb10.y, s3); s3 = fmaf(C.w, fb11.y, s3);
        a0 = fmaf(W.x, s0, a0);
        a1 = fmaf(W.y, s1, a1);
        a2 = fmaf(W.z, s2, a2);
        a3 = fmaf(W.w, s3, a3);
    }

    // write + groupnorm partials (channels 4cg..4cg+3 = groups 2cg, 2cg+1)
    float v0 = a0 + sb[cg*4], v1 = a1 + sb[cg*4+1];
    float v2 = a2 + sb[cg*4+2], v3 = a3 + sb[cg*4+3];
    g_pre[((size_t)b*64 + cg*4    )*HW + pix] = v0;
    g_pre[((size_t)b*64 + cg*4 + 1)*HW + pix] = v1;
    g_pre[((size_t)b*64 + cg*4 + 2)*HW + pix] = v2;
    g_pre[((size_t)b*64 + cg*4 + 3)*HW + pix] = v3;
    float s0 = v0 + v1, q0 = fmaf(v0, v0, v1*v1);
    float s1 = v2 + v3, q1 = fmaf(v2, v2, v3*v3);
#pragma unroll
    for (int o = 16; o > 0; o >>= 1) {
        s0 += __shfl_xor_sync(0xFFFFFFFF, s0, o);
        q0 += __shfl_xor_sync(0xFFFFFFFF, q0, o);
        s1 += __shfl_xor_sync(0xFFFFFFFF, s1, o);
        q1 += __shfl_xor_sync(0xFFFFFFFF, q1, o);
    }
    if ((tid & 31) == 0) {
        g_part[(size_t)blk*32 + 2*cg    ] = make_float2(s0, q0);
        g_part[(size_t)blk*32 + 2*cg + 1] = make_float2(s1, q1);
    }
}

// ---------------------------------------------------------------------------
// Kernel 4a: final stats: reduce 512 block-partials per (b,group).
// ---------------------------------------------------------------------------
__global__ __launch_bounds__(256) void k4a_final()
{
    __shared__ float2 sp[256];
    const int bg = blockIdx.x;              // 0..127
    const int b = bg >> 5, g = bg & 31;
    float s = 0.f, q = 0.f;
    for (int j = threadIdx.x; j < 512; j += 256) {
        float2 v = g_part[(size_t)(b*512 + j)*32 + g];
        s += v.x; q += v.y;
    }
    sp[threadIdx.x] = make_float2(s, q);
    __syncthreads();
    for (int st = 128; st > 0; st >>= 1) {
        if (threadIdx.x < st) {
            sp[threadIdx.x].x += sp[threadIdx.x + st].x;
            sp[threadIdx.x].y += sp[threadIdx.x + st].y;
        }
        __syncthreads();
    }
    if (threadIdx.x == 0) {
        float mean = sp[0].x * (1.f/32768.f);
        float var  = sp[0].y * (1.f/32768.f) - mean*mean;
        g_stats[bg*2]   = mean;
        g_stats[bg*2+1] = rsqrtf(var + 1e-5f);
    }
}

// ---------------------------------------------------------------------------
// Kernel 4b: normalize + affine + exact GELU (float4)
// ---------------------------------------------------------------------------
__global__ __launch_bounds__(256) void k4b_norm(
    const float* __restrict__ gamma,
    const float* __restrict__ beta,
    float* __restrict__ out)
{
    const int i4 = blockIdx.x * 256 + threadIdx.x;
    const int i  = i4 << 2;
    const int c  = (i >> 14) & 63;
    const int b  = i >> 20;
    const int bg = b*32 + (c >> 1);
    const float mean = g_stats[bg*2];
    const float rstd = g_stats[bg*2 + 1];
    const float ga = __ldg(gamma + c), be = __ldg(beta + c);
    float4 v = ((const float4*)g_pre)[i4];
    float4 r;
    float yv;
    yv = (v.x - mean) * rstd * ga + be;
    r.x = 0.5f * yv * (1.f + erff(yv * 0.70710678118654752f));
    yv = (v.y - mean) * rstd * ga + be;
    r.y = 0.5f * yv * (1.f + erff(yv * 0.70710678118654752f));
    yv = (v.z - mean) * rstd * ga + be;
    r.z = 0.5f * yv * (1.f + erff(yv * 0.70710678118654752f));
    yv = (v.w - mean) * rstd * ga + be;
    r.w = 0.5f * yv * (1.f + erff(yv * 0.70710678118654752f));
    ((float4*)out)[i4] = r;
}

// ---------------------------------------------------------------------------
extern "C" void kernel_launch(void* const* d_in, const int* in_sizes, int n_in,
                              void* d_out, int out_size)
{
    const float* x       = (const float*)d_in[0];
    const float* w_off1  = (const float*)d_in[1];
    const float* w_off2  = (const float*)d_in[2];
    const float* w_mask1 = (const float*)d_in[3];
    const float* w_mask2 = (const float*)d_in[4];
    const float* weight  = (const float*)d_in[5];
    const float* bias    = (const float*)d_in[6];
    const float* gamma   = (const float*)d_in[7];
    const float* beta    = (const float*)d_in[8];
    float* out = (float*)d_out;

    cudaFuncSetAttribute(k1_wmma, cudaFuncAttributeMaxDynamicSharedMemorySize, K1_SMEM);
    cudaFuncSetAttribute(k2_wmma, cudaFuncAttributeMaxDynamicSharedMemorySize, K2_SMEM);

    k0_prep <<<64, 256>>>(w_off1, w_mask1, w_off2, w_mask2);
    k1_wmma <<<512, 256, K1_SMEM>>>(x);
    k2_wmma <<<dim3(512, 2), 256, K2_SMEM>>>();
    k3_sample<<<2048, 512>>>(weight, bias);
    k4a_final<<<128, 256>>>();
    k4b_norm<<<4096, 256>>>(gamma, beta, out);
}

// round 8
// speedup vs baseline: 2.9369x; 1.1516x over previous
#include <cuda_runtime.h>
#include <cuda_fp16.h>
#include <mma.h>
#include <math.h>
#include <stdint.h>

using namespace nvcuda;

#define Bdim 4
#define Cdim 64
#define Hdim 128
#define Wdim 128
#define HW (Hdim*Wdim)

#define PADH 72            // halfs per smem row for B tiles (144 B)

// ---------------------------------------------------------------------------
// Device scratch
// ---------------------------------------------------------------------------
__device__ uint4 t1Th[Bdim*HW*8];       // half [pix][64ch] (offset path)
__device__ uint4 t2Th[Bdim*HW*8];       // half [pix][64ch] (mask path)
__device__ uint4 g_x8[Bdim*8*HW];       // half x, channel-oct packed: [b][c8][pix]
__device__ uint4 wB1h[1024];            // half [128 cout][64 cin]  (w_off1 | w_mask1)
__device__ uint4 wB2o[2304];            // half [9 tap][32 cout][64 cin] (w_off2, rows 18-31 zero)
__device__ uint4 wB2m[2304];            // half [9 tap][32 cout][64 cin] (w_mask2, rows 9-31 zero)
__device__ float g_off [Bdim*18*HW];
__device__ float g_mask[Bdim*9*HW];
__device__ float g_pre [Bdim*Cdim*HW];
__device__ float2 g_part[2048*32];      // per-block per-group partial (sum, sumsq)
__device__ float g_stats[256];

// ---------------------------------------------------------------------------
// Kernel 0: weight prep -> half, GEMM-friendly layouts
// ---------------------------------------------------------------------------
__global__ __launch_bounds__(256) void k0_prep(
    const float* __restrict__ w_off1, const float* __restrict__ w_mask1,
    const float* __restrict__ w_off2, const float* __restrict__ w_mask2)
{
    __half* b1  = (__half*)wB1h;
    __half* b2o = (__half*)wB2o;
    __half* b2m = (__half*)wB2m;
    for (int j = blockIdx.x * 256 + threadIdx.x; j < 45056; j += gridDim.x * 256) {
        if (j < 8192) {
            int o = j >> 6, c = j & 63;
            float v = (o < 64) ? w_off1[o*64 + c] : w_mask1[(o-64)*64 + c];
            b1[j] = __float2half_rn(v);
        } else if (j < 26624) {
            int j2 = j - 8192;
            int t = j2 >> 11, o = (j2 >> 6) & 31, c = j2 & 63;
            float v = (o < 18) ? w_off2[o*576 + c*9 + t] : 0.f;
            b2o[j2] = __float2half_rn(v);
        } else {
            int j2 = j - 26624;
            int t = j2 >> 11, o = (j2 >> 6) & 31, c = j2 & 63;
            float v = (o < 9) ? w_mask2[o*576 + c*9 + t] : 0.f;
            b2m[j2] = __float2half_rn(v);
        }
    }
}

// ---------------------------------------------------------------------------
// Kernel 1: both 1x1 convs as one wmma GEMM; also emits g_x8 (oct-packed x).
// ---------------------------------------------------------------------------
#define K1_A    0
#define K1_B    18432                  // 128*144
#define K1_STG  36864
#define K1_SMEM (36864 + 128*132*4)    // 104448 B

__global__ __launch_bounds__(256) void k1_wmma(const float* __restrict__ x)
{
    extern __shared__ char sm[];
    __half* Ah = (__half*)(sm + K1_A);
    __half* Bh = (__half*)(sm + K1_B);
    float*  Sg = (float*) (sm + K1_STG);
    const int tid = threadIdx.x;
    const int wid = tid >> 5, lid = tid & 31;
    const int p0  = blockIdx.x * 128;
    const int b   = p0 >> 14;
    const int pi  = p0 & 16383;

    for (int j = tid; j < 1024; j += 256) {
        int o = j >> 3, seg = j & 7;
        *(uint4*)((char*)Bh + o*144 + seg*16) = wB1h[j];
    }
    const float* xb = x + (size_t)b * 64 * HW + pi;
    for (int j = tid; j < 4096; j += 256) {
        int cp = j >> 7, p = j & 127;
        float va = xb[(2*cp  )*HW + p];
        float vb = xb[(2*cp+1)*HW + p];
        __half2 h = __floats2half2_rn(va, vb);
        *(uint32_t*)((char*)Ah + p*144 + cp*4) = *(uint32_t*)&h;
    }
    __syncthreads();

    // emit oct-packed x gather table: g_x8[(b*8+c8)*HW + pix]
    for (int j = tid; j < 1024; j += 256) {
        int c8 = j >> 7, p = j & 127;
        uint4 v = *(uint4*)((char*)Ah + p*144 + c8*16);
        g_x8[(size_t)((b*8 + c8) << 14) + pi + p] = v;
    }

    wmma::fragment<wmma::accumulator, 16, 16, 16, float> acc[8];
#pragma unroll
    for (int n = 0; n < 8; n++) wmma::fill_fragment(acc[n], 0.f);
    for (int k = 0; k < 4; k++) {
        wmma::fragment<wmma::matrix_a, 16, 16, 16, __half, wmma::row_major> fa;
        wmma::load_matrix_sync(fa, Ah + wid*16*PADH + k*16, PADH);
#pragma unroll
        for (int n = 0; n < 8; n++) {
            wmma::fragment<wmma::matrix_b, 16, 16, 16, __half, wmma::col_major> fb;
            wmma::load_matrix_sync(fb, Bh + n*16*PADH + k*16, PADH);
            wmma::mma_sync(acc[n], fa, fb, acc[n]);
        }
    }
    float* st = Sg + wid*16*132;
#pragma unroll
    for (int n = 0; n < 8; n++)
        wmma::store_matrix_sync(st + n*16, acc[n], 132, wmma::mem_row_major);
    __syncwarp();
#pragma unroll
    for (int i = 0; i < 8; i++) {
        int item  = i*32 + lid;
        int row   = item >> 4;
        int chunk = item & 15;
        const float* s = st + row*132 + chunk*8;
        uint4 o4;
        __half2 h;
        h = __floats2half2_rn(s[0], s[1]); o4.x = *(uint32_t*)&h;
        h = __floats2half2_rn(s[2], s[3]); o4.y = *(uint32_t*)&h;
        h = __floats2half2_rn(s[4], s[5]); o4.z = *(uint32_t*)&h;
        h = __floats2half2_rn(s[6], s[7]); o4.w = *(uint32_t*)&h;
        int gp = p0 + wid*16 + row;
        if (chunk < 8) t1Th[(size_t)gp*8 + chunk]     = o4;
        else           t2Th[(size_t)gp*8 + (chunk-8)] = o4;
    }
}

// ---------------------------------------------------------------------------
// Kernel 2: 3x3 convs via 3-row buffer + shifted wmma fragments (no im2col).
// A: 3 rows x 130 pixels x 160B stride (80 halfs); dx shift = +-160B, which
// keeps wmma's 32B alignment. B: 9 tap sections, [32 cout][64ch], 144B rows.
// ---------------------------------------------------------------------------
#define K2_AROW  10400                 // halfs per dy row buffer (130*80)
#define K2_ABYTES 62400                // 3*130*160
#define K2_B     62400
#define K2_BSECT 4608
#define K2_SMEM  (62400 + 9*4608)      // 103872 B

__global__ __launch_bounds__(256) void k2_wmma()
{
    extern __shared__ char sm[];
    __half* Ah = (__half*)sm;
    __half* Bh = (__half*)(sm + K2_B);
    float*  Sg = (float*)sm;             // overlay on A after MMA phase
    const int tid = threadIdx.x;
    const int wid = tid >> 5, lid = tid & 31;
    const int bx = blockIdx.x;
    const int b = bx >> 7, y = bx & 127;
    const int path = blockIdx.y;

    // B weights: [9][32][8 uint4] at 144B rows
    const uint4* wsrc = path ? wB2m : wB2o;
    for (int j = tid; j < 2304; j += 256) {
        int t = j >> 8, o = (j >> 3) & 31, seg = j & 7;
        *(uint4*)((char*)Bh + t*K2_BSECT + o*144 + seg*16) = wsrc[j];
    }
    // A: 3 source rows (y-1, y, y+1), buffer pixel i = image pixel i-1
    const uint4* src = path ? t2Th : t1Th;
    const uint4 z4 = make_uint4(0u,0u,0u,0u);
    for (int j = tid; j < 3120; j += 256) {       // 3 dy * 130 pix * 8 seg
        int dy = j / 1040;
        int r  = j - dy*1040;
        int p  = r >> 3, seg = r & 7;
        int yy = y + dy - 1;
        int px = p - 1;
        uint4 v = z4;
        if ((unsigned)yy < 128u && (unsigned)px < 128u)
            v = src[(size_t)((b << 14) + (yy << 7) + px) * 8 + seg];
        *(uint4*)((char*)Ah + dy*20800 + p*160 + seg*16) = v;
    }
    __syncthreads();

    wmma::fragment<wmma::accumulator, 16, 16, 16, float> acc[2];
    wmma::fill_fragment(acc[0], 0.f);
    wmma::fill_fragment(acc[1], 0.f);
    for (int dy = 0; dy < 3; dy++) {
        const __half* Ad = Ah + dy*K2_AROW + wid*16*80;
#pragma unroll
        for (int dx = 0; dx < 3; dx++) {
            const __half* Adx = Ad + dx*80;          // pixel base = wid*16+dx (buffer idx)
            const __half* Bt  = Bh + (dy*3 + dx)*(K2_BSECT/2);
#pragma unroll
            for (int k = 0; k < 4; k++) {
                wmma::fragment<wmma::matrix_a, 16, 16, 16, __half, wmma::row_major> fa;
                wmma::load_matrix_sync(fa, Adx + k*16, 80);
#pragma unroll
                for (int n = 0; n < 2; n++) {
                    wmma::fragment<wmma::matrix_b, 16, 16, 16, __half, wmma::col_major> fb;
                    wmma::load_matrix_sync(fb, Bt + n*16*PADH + k*16, PADH);
                    wmma::mma_sync(acc[n], fa, fb, acc[n]);
                }
            }
        }
    }
    __syncthreads();   // all A reads done before staging overlay writes

    float* st = Sg + wid*16*36;
    wmma::store_matrix_sync(st,      acc[0], 36, wmma::mem_row_major);
    wmma::store_matrix_sync(st + 16, acc[1], 36, wmma::mem_row_major);
    __syncwarp();

    const int p_ = lid & 15;
    const int oh = lid >> 4;
    const int pix = y*Wdim + wid*16 + p_;
    if (path == 0) {
#pragma unroll
        for (int j = 0; j < 9; j++) {
            int o = oh*9 + j;
            g_off[((size_t)b*18 + o)*HW + pix] = st[p_*36 + o];
        }
    } else if (oh == 0) {
#pragma unroll
        for (int j = 0; j < 9; j++) {
            float v = st[p_*36 + j];
            g_mask[((size_t)b*9 + j)*HW + pix] = 1.f / (1.f + expf(-v));
        }
    }
}

// ---------------------------------------------------------------------------
// Kernel 3: deformable gather (8-channel LDG.128) + einsum + bias,
// fused groupnorm partials. Block = 64 pixels x 512 threads (8 ch-octs).
// ---------------------------------------------------------------------------
__global__ __launch_bounds__(512) void k3_sample(
    const float* __restrict__ wgt,
    const float* __restrict__ bias)
{
    __shared__ float4 sw8[9*8*2];       // [k][cg] weight oct (2x float4)
    __shared__ float  sb[64];
    __shared__ int4   sI[9*64];
    __shared__ float4 sC[9*64];

    const int tid = threadIdx.x;
    if (tid < 144) {
        int k = tid / 16, idx = tid & 15;
        int cg = idx >> 1, h = idx & 1;
        int c0 = cg*8 + h*4;
        sw8[(k*8 + cg)*2 + h] = make_float4(wgt[(c0  )*9 + k], wgt[(c0+1)*9 + k],
                                            wgt[(c0+2)*9 + k], wgt[(c0+3)*9 + k]);
    }
    if (tid >= 448) sb[tid - 448] = bias[tid - 448];

    const int blk = blockIdx.x;             // 1024
    const int b   = blk >> 8;               // 256 blocks per batch
    const int p0  = (blk & 255) * 64;       // pixel within image

    for (int e = tid; e < 576; e += 512) {
        const int k = e >> 6;               // 0..8
        const int p = e & 63;
        const int pix = p0 + p;
        const int gy = pix >> 7, gx = pix & 127;
        const float* offb = g_off  + (size_t)b * 18 * HW;
        const float* mkb  = g_mask + (size_t)b * 9  * HW;
        float oy = offb[(2*k  )*HW + pix];
        float ox = offb[(2*k+1)*HW + pix];
        float mk = mkb [ k     *HW + pix];
        float py  = oy + (float)gy + (float)(k/3 - 1);
        float pxx = ox + (float)gx + (float)(k%3 - 1);
        float y0f = floorf(py),  x0f = floorf(pxx);
        float wy1 = py - y0f,    wx1 = pxx - x0f;
        int   y0  = (int)y0f,    xx0 = (int)x0f;
        int cy0 = min(max(y0,   0), Hdim-1), cy1 = min(max(y0+1, 0), Hdim-1);
        int cx0 = min(max(xx0,  0), Wdim-1), cx1 = min(max(xx0+1,0), Wdim-1);
        float vy0 = (y0   >= 0 && y0   < Hdim) ? 1.f : 0.f;
        float vy1 = (y0+1 >= 0 && y0+1 < Hdim) ? 1.f : 0.f;
        float vx0 = (xx0  >= 0 && xx0  < Wdim) ? 1.f : 0.f;
        float vx1 = (xx0+1>= 0 && xx0+1< Wdim) ? 1.f : 0.f;
        float ay0 = (1.f - wy1) * vy0 * mk;
        float ay1 = wy1 * vy1 * mk;
        float ax0 = (1.f - wx1) * vx0;
        float ax1 = wx1 * vx1;
        sI[k*64 + p] = make_int4(cy0*Wdim + cx0, cx1 - cx0, (cy1 - cy0)*Wdim, 0);
        sC[k*64 + p] = make_float4(ay0*ax0, ay0*ax1, ay1*ax0, ay1*ax1);
    }
    __syncthreads();

    const int p   = tid & 63;
    const int cg  = tid >> 6;               // 0..7 -> channels cg*8..cg*8+7
    const int pix = p0 + p;
    const uint4* x8 = g_x8 + (size_t)((b*8 + cg) << 14);

    float a0=0.f,a1=0.f,a2=0.f,a3=0.f,a4=0.f,a5=0.f,a6=0.f,a7=0.f;
    for (int k = 0; k < 9; k++) {
        int4   I  = sI[k*64 + p];
        float4 C  = sC[k*64 + p];
        float4 Wa = sw8[(k*8 + cg)*2];
        float4 Wb = sw8[(k*8 + cg)*2 + 1];
        uint4 u00 = __ldg(x8 + I.x);
        uint4 u01 = __ldg(x8 + I.x + I.y);
        uint4 u10 = __ldg(x8 + I.x + I.z);
        uint4 u11 = __ldg(x8 + I.x + I.z + I.y);
        float2 f00, f01, f10, f11;
        float s;
        // ch 0,1
        f00 = __half22float2(*(__half2*)&u00.x); f01 = __half22float2(*(__half2*)&u01.x);
        f10 = __half22float2(*(__half2*)&u10.x); f11 = __half22float2(*(__half2*)&u11.x);
        s = C.x*f00.x; s = fmaf(C.y,f01.x,s); s = fmaf(C.z,f10.x,s); s = fmaf(C.w,f11.x,s); a0 = fmaf(Wa.x, s, a0);
        s = C.x*f00.y; s = fmaf(C.y,f01.y,s); s = fmaf(C.z,f10.y,s); s = fmaf(C.w,f11.y,s); a1 = fmaf(Wa.y, s, a1);
        // ch 2,3
        f00 = __half22float2(*(__half2*)&u00.y); f01 = __half22float2(*(__half2*)&u01.y);
        f10 = __half22float2(*(__half2*)&u10.y); f11 = __half22float2(*(__half2*)&u11.y);
        s = C.x*f00.x; s = fmaf(C.y,f01.x,s); s = fmaf(C.z,f10.x,s); s = fmaf(C.w,f11.x,s); a2 = fmaf(Wa.z, s, a2);
        s = C.x*f00.y; s = fmaf(C.y,f01.y,s); s = fmaf(C.z,f10.y,s); s = fmaf(C.w,f11.y,s); a3 = fmaf(Wa.w, s, a3);
        // ch 4,5
        f00 = __half22float2(*(__half2*)&u00.z); f01 = __half22float2(*(__half2*)&u01.z);
        f10 = __half22float2(*(__half2*)&u10.z); f11 = __half22float2(*(__half2*)&u11.z);
        s = C.x*f00.x; s = fmaf(C.y,f01.x,s); s = fmaf(C.z,f10.x,s); s = fmaf(C.w,f11.x,s); a4 = fmaf(Wb.x, s, a4);
        s = C.x*f00.y; s = fmaf(C.y,f01.y,s); s = fmaf(C.z,f10.y,s); s = fmaf(C.w,f11.y,s); a5 = fmaf(Wb.y, s, a5);
        // ch 6,7
        f00 = __half22float2(*(__half2*)&u00.w); f01 = __half22float2(*(__half2*)&u01.w);
        f10 = __half22float2(*(__half2*)&u10.w); f11 = __half22float2(*(__half2*)&u11.w);
        s = C.x*f00.x; s = fmaf(C.y,f01.x,s); s = fmaf(C.z,f10.x,s); s = fmaf(C.w,f11.x,s); a6 = fmaf(Wb.z, s, a6);
        s = C.x*f00.y; s = fmaf(C.y,f01.y,s); s = fmaf(C.z,f10.y,s); s = fmaf(C.w,f11.y,s); a7 = fmaf(Wb.w, s, a7);
    }

    // write + groupnorm partials (channels 8cg..8cg+7 = groups 4cg..4cg+3)
    const int c0 = cg*8;
    float v0 = a0 + sb[c0  ], v1 = a1 + sb[c0+1];
    float v2 = a2 + sb[c0+2], v3 = a3 + sb[c0+3];
    float v4 = a4 + sb[c0+4], v5 = a5 + sb[c0+5];
    float v6 = a6 + sb[c0+6], v7 = a7 + sb[c0+7];
    g_pre[((size_t)b*64 + c0    )*HW + pix] = v0;
    g_pre[((size_t)b*64 + c0 + 1)*HW + pix] = v1;
    g_pre[((size_t)b*64 + c0 + 2)*HW + pix] = v2;
    g_pre[((size_t)b*64 + c0 + 3)*HW + pix] = v3;
    g_pre[((size_t)b*64 + c0 + 4)*HW + pix] = v4;
    g_pre[((size_t)b*64 + c0 + 5)*HW + pix] = v5;
    g_pre[((size_t)b*64 + c0 + 6)*HW + pix] = v6;
    g_pre[((size_t)b*64 + c0 + 7)*HW + pix] = v7;
    float s0 = v0+v1, q0 = fmaf(v0,v0, v1*v1);
    float s1 = v2+v3, q1 = fmaf(v2,v2, v3*v3);
    float s2 = v4+v5, q2 = fmaf(v4,v4, v5*v5);
    float s3 = v6+v7, q3 = fmaf(v6,v6, v7*v7);
#pragma unroll
    for (int o = 16; o > 0; o >>= 1) {
        s0 += __shfl_xor_sync(0xFFFFFFFF, s0, o);
        q0 += __shfl_xor_sync(0xFFFFFFFF, q0, o);
        s1 += __shfl_xor_sync(0xFFFFFFFF, s1, o);
        q1 += __shfl_xor_sync(0xFFFFFFFF, q1, o);
        s2 += __shfl_xor_sync(0xFFFFFFFF, s2, o);
        q2 += __shfl_xor_sync(0xFFFFFFFF, q2, o);
        s3 += __shfl_xor_sync(0xFFFFFFFF, s3, o);
        q3 += __shfl_xor_sync(0xFFFFFFFF, q3, o);
    }
    if ((tid & 31) == 0) {
        // two warps per (cg): lane-0 warps of pixel halves both write; make
        // them distinct partial slots via warp id parity
        int wslot = (tid >> 5) & 1;          // 0 or 1 within the cg pair
        float2* dst = &g_part[((size_t)blk*2 + wslot)*32 + 4*cg];
        dst[0] = make_float2(s0, q0);
        dst[1] = make_float2(s1, q1);
        dst[2] = make_float2(s2, q2);
        dst[3] = make_float2(s3, q3);
    }
}

// ---------------------------------------------------------------------------
// Kernel 4a: final stats: reduce 2048 warp-partials per (b,group).
// ---------------------------------------------------------------------------
__global__ __launch_bounds__(256) void k4a_final()
{
    __shared__ float2 sp[256];
    const int bg = blockIdx.x;              // 0..127
    const int b = bg >> 5, g = bg & 31;
    float s = 0.f, q = 0.f;
    for (int j = threadIdx.x; j < 512; j += 256) {
        float2 v = g_part[(size_t)(b*512 + j)*32 + g];
        s += v.x; q += v.y;
    }
    sp[threadIdx.x] = make_float2(s, q);
    __syncthreads();
    for (int st = 128; st > 0; st >>= 1) {
        if (threadIdx.x < st) {
            sp[threadIdx.x].x += sp[threadIdx.x + st].x;
            sp[threadIdx.x].y += sp[threadIdx.x + st].y;
        }
        __syncthreads();
    }
    if (threadIdx.x == 0) {
        float mean = sp[0].x * (1.f/32768.f);
        float var  = sp[0].y * (1.f/32768.f) - mean*mean;
        g_stats[bg*2]   = mean;
        g_stats[bg*2+1] = rsqrtf(var + 1e-5f);
    }
}

// ---------------------------------------------------------------------------
// Kernel 4b: normalize + affine + exact GELU (float4)
// ---------------------------------------------------------------------------
__global__ __launch_bounds__(256) void k4b_norm(
    const float* __restrict__ gamma,
    const float* __restrict__ beta,
    float* __restrict__ out)
{
    const int i4 = blockIdx.x * 256 + threadIdx.x;
    const int i  = i4 << 2;
    const int c  = (i >> 14) & 63;
    const int b  = i >> 20;
    const int bg = b*32 + (c >> 1);
    const float mean = g_stats[bg*2];
    const float rstd = g_stats[bg*2 + 1];
    const float ga = __ldg(gamma + c), be = __ldg(beta + c);
    float4 v = ((const float4*)g_pre)[i4];
    float4 r;
    float yv;
    yv = (v.x - mean) * rstd * ga + be;
    r.x = 0.5f * yv * (1.f + erff(yv * 0.70710678118654752f));
    yv = (v.y - mean) * rstd * ga + be;
    r.y = 0.5f * yv * (1.f + erff(yv * 0.70710678118654752f));
    yv = (v.z - mean) * rstd * ga + be;
    r.z = 0.5f * yv * (1.f + erff(yv * 0.70710678118654752f));
    yv = (v.w - mean) * rstd * ga + be;
    r.w = 0.5f * yv * (1.f + erff(yv * 0.70710678118654752f));
    ((float4*)out)[i4] = r;
}

// ---------------------------------------------------------------------------
extern "C" void kernel_launch(void* const* d_in, const int* in_sizes, int n_in,
                              void* d_out, int out_size)
{
    const float* x       = (const float*)d_in[0];
    const float* w_off1  = (const float*)d_in[1];
    const float* w_off2  = (const float*)d_in[2];
    const float* w_mask1 = (const float*)d_in[3];
    const float* w_mask2 = (const float*)d_in[4];
    const float* weight  = (const float*)d_in[5];
    const float* bias    = (const float*)d_in[6];
    const float* gamma   = (const float*)d_in[7];
    const float* beta    = (const float*)d_in[8];
    float* out = (float*)d_out;

    cudaFuncSetAttribute(k1_wmma, cudaFuncAttributeMaxDynamicSharedMemorySize, K1_SMEM);
    cudaFuncSetAttribute(k2_wmma, cudaFuncAttributeMaxDynamicSharedMemorySize, K2_SMEM);

    k0_prep <<<64, 256>>>(w_off1, w_mask1, w_off2, w_mask2);
    k1_wmma <<<512, 256, K1_SMEM>>>(x);
    k2_wmma <<<dim3(512, 2), 256, K2_SMEM>>>();
    k3_sample<<<1024, 512>>>(weight, bias);
    k4a_final<<<128, 256>>>();
    k4b_norm<<<4096, 256>>>(gamma, beta, out);
}

// round 9
// speedup vs baseline: 2.9418x; 1.0017x over previous
#include <cuda_runtime.h>
#include <cuda_fp16.h>
#include <mma.h>
#include <math.h>
#include <stdint.h>

using namespace nvcuda;

#define Bdim 4
#define Cdim 64
#define Hdim 128
#define Wdim 128
#define HW (Hdim*Wdim)

#define PADH 72            // halfs per smem row for B tiles (144 B)

// ---------------------------------------------------------------------------
// Device scratch
// ---------------------------------------------------------------------------
__device__ uint4 t1Th[Bdim*HW*8];       // half [pix][64ch] (offset path)
__device__ uint4 t2Th[Bdim*HW*8];       // half [pix][64ch] (mask path)
__device__ uint4 g_x8[Bdim*8*HW];       // half x, channel-oct packed: [b][c8][pix]
__device__ uint4 wB1h[1024];            // half [128 cout][64 cin]  (w_off1 | w_mask1)
__device__ uint4 wB2o[2304];            // half [9 tap][32 cout][64 cin] (w_off2, rows 18-31 zero)
__device__ uint4 wB2m[2304];            // half [9 tap][32 cout][64 cin] (w_mask2, rows 9-31 zero)
__device__ float g_off [Bdim*18*HW];
__device__ float g_mask[Bdim*9*HW];
__device__ float g_pre [Bdim*Cdim*HW];
__device__ float2 g_part[2048*32];      // per-warp-slot per-group partial (sum, sumsq)
__device__ float g_stats[256];

// ---------------------------------------------------------------------------
// Kernel 0: weight prep -> half, GEMM-friendly layouts
// ---------------------------------------------------------------------------
__global__ __launch_bounds__(256) void k0_prep(
    const float* __restrict__ w_off1, const float* __restrict__ w_mask1,
    const float* __restrict__ w_off2, const float* __restrict__ w_mask2)
{
    __half* b1  = (__half*)wB1h;
    __half* b2o = (__half*)wB2o;
    __half* b2m = (__half*)wB2m;
    for (int j = blockIdx.x * 256 + threadIdx.x; j < 45056; j += gridDim.x * 256) {
        if (j < 8192) {
            int o = j >> 6, c = j & 63;
            float v = (o < 64) ? w_off1[o*64 + c] : w_mask1[(o-64)*64 + c];
            b1[j] = __float2half_rn(v);
        } else if (j < 26624) {
            int j2 = j - 8192;
            int t = j2 >> 11, o = (j2 >> 6) & 31, c = j2 & 63;
            float v = (o < 18) ? w_off2[o*576 + c*9 + t] : 0.f;
            b2o[j2] = __float2half_rn(v);
        } else {
            int j2 = j - 26624;
            int t = j2 >> 11, o = (j2 >> 6) & 31, c = j2 & 63;
            float v = (o < 9) ? w_mask2[o*576 + c*9 + t] : 0.f;
            b2m[j2] = __float2half_rn(v);
        }
    }
}

// ---------------------------------------------------------------------------
// Kernel 1: both 1x1 convs as one wmma GEMM; also emits g_x8 (oct-packed x).
// ---------------------------------------------------------------------------
#define K1_A    0
#define K1_B    18432                  // 128*144
#define K1_STG  36864
#define K1_SMEM (36864 + 128*132*4)    // 104448 B

__global__ __launch_bounds__(256) void k1_wmma(const float* __restrict__ x)
{
    extern __shared__ char sm[];
    __half* Ah = (__half*)(sm + K1_A);
    __half* Bh = (__half*)(sm + K1_B);
    float*  Sg = (float*) (sm + K1_STG);
    const int tid = threadIdx.x;
    const int wid = tid >> 5, lid = tid & 31;
    const int p0  = blockIdx.x * 128;
    const int b   = p0 >> 14;
    const int pi  = p0 & 16383;

    for (int j = tid; j < 1024; j += 256) {
        int o = j >> 3, seg = j & 7;
        *(uint4*)((char*)Bh + o*144 + seg*16) = wB1h[j];
    }
    const float* xb = x + (size_t)b * 64 * HW + pi;
    for (int j = tid; j < 4096; j += 256) {
        int cp = j >> 7, p = j & 127;
        float va = xb[(2*cp  )*HW + p];
        float vb = xb[(2*cp+1)*HW + p];
        __half2 h = __floats2half2_rn(va, vb);
        *(uint32_t*)((char*)Ah + p*144 + cp*4) = *(uint32_t*)&h;
    }
    __syncthreads();

    // emit oct-packed x gather table: g_x8[(b*8+c8)*HW + pix]
    for (int j = tid; j < 1024; j += 256) {
        int c8 = j >> 7, p = j & 127;
        uint4 v = *(uint4*)((char*)Ah + p*144 + c8*16);
        g_x8[(size_t)((b*8 + c8) << 14) + pi + p] = v;
    }

    wmma::fragment<wmma::accumulator, 16, 16, 16, float> acc[8];
#pragma unroll
    for (int n = 0; n < 8; n++) wmma::fill_fragment(acc[n], 0.f);
    for (int k = 0; k < 4; k++) {
        wmma::fragment<wmma::matrix_a, 16, 16, 16, __half, wmma::row_major> fa;
        wmma::load_matrix_sync(fa, Ah + wid*16*PADH + k*16, PADH);
#pragma unroll
        for (int n = 0; n < 8; n++) {
            wmma::fragment<wmma::matrix_b, 16, 16, 16, __half, wmma::col_major> fb;
            wmma::load_matrix_sync(fb, Bh + n*16*PADH + k*16, PADH);
            wmma::mma_sync(acc[n], fa, fb, acc[n]);
        }
    }
    float* st = Sg + wid*16*132;
#pragma unroll
    for (int n = 0; n < 8; n++)
        wmma::store_matrix_sync(st + n*16, acc[n], 132, wmma::mem_row_major);
    __syncwarp();
#pragma unroll
    for (int i = 0; i < 8; i++) {
        int item  = i*32 + lid;
        int row   = item >> 4;
        int chunk = item & 15;
        const float* s = st + row*132 + chunk*8;
        uint4 o4;
        __half2 h;
        h = __floats2half2_rn(s[0], s[1]); o4.x = *(uint32_t*)&h;
        h = __floats2half2_rn(s[2], s[3]); o4.y = *(uint32_t*)&h;
        h = __floats2half2_rn(s[4], s[5]); o4.z = *(uint32_t*)&h;
        h = __floats2half2_rn(s[6], s[7]); o4.w = *(uint32_t*)&h;
        int gp = p0 + wid*16 + row;
        if (chunk < 8) t1Th[(size_t)gp*8 + chunk]     = o4;
        else           t2Th[(size_t)gp*8 + (chunk-8)] = o4;
    }
}

// ---------------------------------------------------------------------------
// Kernel 2: 3x3 convs via 3-row buffer + shifted wmma fragments (no im2col).
// ---------------------------------------------------------------------------
#define K2_AROW  10400                 // halfs per dy row buffer (130*80)
#define K2_B     62400
#define K2_BSECT 4608
#define K2_SMEM  (62400 + 9*4608)      // 103872 B

__global__ __launch_bounds__(256) void k2_wmma()
{
    extern __shared__ char sm[];
    __half* Ah = (__half*)sm;
    __half* Bh = (__half*)(sm + K2_B);
    float*  Sg = (float*)sm;             // overlay on A after MMA phase
    const int tid = threadIdx.x;
    const int wid = tid >> 5, lid = tid & 31;
    const int bx = blockIdx.x;
    const int b = bx >> 7, y = bx & 127;
    const int path = blockIdx.y;

    const uint4* wsrc = path ? wB2m : wB2o;
    for (int j = tid; j < 2304; j += 256) {
        int t = j >> 8, o = (j >> 3) & 31, seg = j & 7;
        *(uint4*)((char*)Bh + t*K2_BSECT + o*144 + seg*16) = wsrc[j];
    }
    const uint4* src = path ? t2Th : t1Th;
    const uint4 z4 = make_uint4(0u,0u,0u,0u);
    for (int j = tid; j < 3120; j += 256) {       // 3 dy * 130 pix * 8 seg
        int dy = j / 1040;
        int r  = j - dy*1040;
        int p  = r >> 3, seg = r & 7;
        int yy = y + dy - 1;
        int px = p - 1;
        uint4 v = z4;
        if ((unsigned)yy < 128u && (unsigned)px < 128u)
            v = src[(size_t)((b << 14) + (yy << 7) + px) * 8 + seg];
        *(uint4*)((char*)Ah + dy*20800 + p*160 + seg*16) = v;
    }
    __syncthreads();

    wmma::fragment<wmma::accumulator, 16, 16, 16, float> acc[2];
    wmma::fill_fragment(acc[0], 0.f);
    wmma::fill_fragment(acc[1], 0.f);
    for (int dy = 0; dy < 3; dy++) {
        const __half* Ad = Ah + dy*K2_AROW + wid*16*80;
#pragma unroll
        for (int dx = 0; dx < 3; dx++) {
            const __half* Adx = Ad + dx*80;
            const __half* Bt  = Bh + (dy*3 + dx)*(K2_BSECT/2);
#pragma unroll
            for (int k = 0; k < 4; k++) {
                wmma::fragment<wmma::matrix_a, 16, 16, 16, __half, wmma::row_major> fa;
                wmma::load_matrix_sync(fa, Adx + k*16, 80);
#pragma unroll
                for (int n = 0; n < 2; n++) {
                    wmma::fragment<wmma::matrix_b, 16, 16, 16, __half, wmma::col_major> fb;
                    wmma::load_matrix_sync(fb, Bt + n*16*PADH + k*16, PADH);
                    wmma::mma_sync(acc[n], fa, fb, acc[n]);
                }
            }
        }
    }
    __syncthreads();

    float* st = Sg + wid*16*36;
    wmma::store_matrix_sync(st,      acc[0], 36, wmma::mem_row_major);
    wmma::store_matrix_sync(st + 16, acc[1], 36, wmma::mem_row_major);
    __syncwarp();

    const int p_ = lid & 15;
    const int oh = lid >> 4;
    const int pix = y*Wdim + wid*16 + p_;
    if (path == 0) {
#pragma unroll
        for (int j = 0; j < 9; j++) {
            int o = oh*9 + j;
            g_off[((size_t)b*18 + o)*HW + pix] = st[p_*36 + o];
        }
    } else if (oh == 0) {
#pragma unroll
        for (int j = 0; j < 9; j++) {
            float v = st[p_*36 + j];
            g_mask[((size_t)b*9 + j)*HW + pix] = 1.f / (1.f + expf(-v));
        }
    }
}

// ---------------------------------------------------------------------------
// Kernel 3: deformable gather (8-channel LDG.128) + einsum + bias,
// SOFTWARE-PIPELINED tap loop (double-buffered loads: MLP 8/warp).
// Block = 64 pixels x 512 threads (8 ch-octs). Fused GN partials.
// ---------------------------------------------------------------------------
__global__ __launch_bounds__(512, 2) void k3_sample(
    const float* __restrict__ wgt,
    const float* __restrict__ bias)
{
    __shared__ float4 sw8[9*8*2];       // [k][cg] weight oct (2x float4)
    __shared__ float  sb[64];
    __shared__ int4   sI[9*64];
    __shared__ float4 sC[9*64];

    const int tid = threadIdx.x;
    if (tid < 144) {
        int k = tid / 16, idx = tid & 15;
        int cg = idx >> 1, h = idx & 1;
        int c0 = cg*8 + h*4;
        sw8[(k*8 + cg)*2 + h] = make_float4(wgt[(c0  )*9 + k], wgt[(c0+1)*9 + k],
                                            wgt[(c0+2)*9 + k], wgt[(c0+3)*9 + k]);
    }
    if (tid >= 448) sb[tid - 448] = bias[tid - 448];

    const int blk = blockIdx.x;             // 1024
    const int b   = blk >> 8;               // 256 blocks per batch
    const int p0  = (blk & 255) * 64;       // pixel within image

    for (int e = tid; e < 576; e += 512) {
        const int k = e >> 6;               // 0..8
        const int p = e & 63;
        const int pix = p0 + p;
        const int gy = pix >> 7, gx = pix & 127;
        const float* offb = g_off  + (size_t)b * 18 * HW;
        const float* mkb  = g_mask + (size_t)b * 9  * HW;
        float oy = offb[(2*k  )*HW + pix];
        float ox = offb[(2*k+1)*HW + pix];
        float mk = mkb [ k     *HW + pix];
        float py  = oy + (float)gy + (float)(k/3 - 1);
        float pxx = ox + (float)gx + (float)(k%3 - 1);
        float y0f = floorf(py),  x0f = floorf(pxx);
        float wy1 = py - y0f,    wx1 = pxx - x0f;
        int   y0  = (int)y0f,    xx0 = (int)x0f;
        int cy0 = min(max(y0,   0), Hdim-1), cy1 = min(max(y0+1, 0), Hdim-1);
        int cx0 = min(max(xx0,  0), Wdim-1), cx1 = min(max(xx0+1,0), Wdim-1);
        float vy0 = (y0   >= 0 && y0   < Hdim) ? 1.f : 0.f;
        float vy1 = (y0+1 >= 0 && y0+1 < Hdim) ? 1.f : 0.f;
        float vx0 = (xx0  >= 0 && xx0  < Wdim) ? 1.f : 0.f;
        float vx1 = (xx0+1>= 0 && xx0+1< Wdim) ? 1.f : 0.f;
        float ay0 = (1.f - wy1) * vy0 * mk;
        float ay1 = wy1 * vy1 * mk;
        float ax0 = (1.f - wx1) * vx0;
        float ax1 = wx1 * vx1;
        sI[k*64 + p] = make_int4(cy0*Wdim + cx0, cx1 - cx0, (cy1 - cy0)*Wdim, 0);
        sC[k*64 + p] = make_float4(ay0*ax0, ay0*ax1, ay1*ax0, ay1*ax1);
    }
    __syncthreads();

    const int p   = tid & 63;
    const int cg  = tid >> 6;               // 0..7 -> channels cg*8..cg*8+7
    const int pix = p0 + p;
    const uint4* x8 = g_x8 + (size_t)((b*8 + cg) << 14);

    float a0=0.f,a1=0.f,a2=0.f,a3=0.f,a4=0.f,a5=0.f,a6=0.f,a7=0.f;

    // prologue: load tap 0
    int4   I = sI[p];
    float4 C = sC[p];
    uint4 u00 = __ldg(x8 + I.x);
    uint4 u01 = __ldg(x8 + I.x + I.y);
    uint4 u10 = __ldg(x8 + I.x + I.z);
    uint4 u11 = __ldg(x8 + I.x + I.z + I.y);

#pragma unroll
    for (int k = 0; k < 9; k++) {
        // prefetch tap k+1 (issues 4 independent LDG.128 before this tap's math)
        uint4 n00, n01, n10, n11;
        int4 In; float4 Cn;
        if (k < 8) {
            In = sI[(k+1)*64 + p];
            Cn = sC[(k+1)*64 + p];
            n00 = __ldg(x8 + In.x);
            n01 = __ldg(x8 + In.x + In.y);
            n10 = __ldg(x8 + In.x + In.z);
            n11 = __ldg(x8 + In.x + In.z + In.y);
        }
        float4 Wa = sw8[(k*8 + cg)*2];
        float4 Wb = sw8[(k*8 + cg)*2 + 1];
        float2 f00, f01, f10, f11;
        float s;
        // ch 0,1
        f00 = __half22float2(*(__half2*)&u00.x); f01 = __half22float2(*(__half2*)&u01.x);
        f10 = __half22float2(*(__half2*)&u10.x); f11 = __half22float2(*(__half2*)&u11.x);
        s = C.x*f00.x; s = fmaf(C.y,f01.x,s); s = fmaf(C.z,f10.x,s); s = fmaf(C.w,f11.x,s); a0 = fmaf(Wa.x, s, a0);
        s = C.x*f00.y; s = fmaf(C.y,f01.y,s); s = fmaf(C.z,f10.y,s); s = fmaf(C.w,f11.y,s); a1 = fmaf(Wa.y, s, a1);
        // ch 2,3
        f00 = __half22float2(*(__half2*)&u00.y); f01 = __half22float2(*(__half2*)&u01.y);
        f10 = __half22float2(*(__half2*)&u10.y); f11 = __half22float2(*(__half2*)&u11.y);
        s = C.x*f00.x; s = fmaf(C.y,f01.x,s); s = fmaf(C.z,f10.x,s); s = fmaf(C.w,f11.x,s); a2 = fmaf(Wa.z, s, a2);
        s = C.x*f00.y; s = fmaf(C.y,f01.y,s); s = fmaf(C.z,f10.y,s); s = fmaf(C.w,f11.y,s); a3 = fmaf(Wa.w, s, a3);
        // ch 4,5
        f00 = __half22float2(*(__half2*)&u00.z); f01 = __half22float2(*(__half2*)&u01.z);
        f10 = __half22float2(*(__half2*)&u10.z); f11 = __half22float2(*(__half2*)&u11.z);
        s = C.x*f00.x; s = fmaf(C.y,f01.x,s); s = fmaf(C.z,f10.x,s); s = fmaf(C.w,f11.x,s); a4 = fmaf(Wb.x, s, a4);
        s = C.x*f00.y; s = fmaf(C.y,f01.y,s); s = fmaf(C.z,f10.y,s); s = fmaf(C.w,f11.y,s); a5 = fmaf(Wb.y, s, a5);
        // ch 6,7
        f00 = __half22float2(*(__half2*)&u00.w); f01 = __half22float2(*(__half2*)&u01.w);
        f10 = __half22float2(*(__half2*)&u10.w); f11 = __half22float2(*(__half2*)&u11.w);
        s = C.x*f00.x; s = fmaf(C.y,f01.x,s); s = fmaf(C.z,f10.x,s); s = fmaf(C.w,f11.x,s); a6 = fmaf(Wb.z, s, a6);
        s = C.x*f00.y; s = fmaf(C.y,f01.y,s); s = fmaf(C.z,f10.y,s); s = fmaf(C.w,f11.y,s); a7 = fmaf(Wb.w, s, a7);
        // rotate buffers
        if (k < 8) { I = In; C = Cn; u00 = n00; u01 = n01; u10 = n10; u11 = n11; }
    }

    // write + groupnorm partials (channels 8cg..8cg+7 = groups 4cg..4cg+3)
    const int c0 = cg*8;
    float v0 = a0 + sb[c0  ], v1 = a1 + sb[c0+1];
    float v2 = a2 + sb[c0+2], v3 = a3 + sb[c0+3];
    float v4 = a4 + sb[c0+4], v5 = a5 + sb[c0+5];
    float v6 = a6 + sb[c0+6], v7 = a7 + sb[c0+7];
    g_pre[((size_t)b*64 + c0    )*HW + pix] = v0;
    g_pre[((size_t)b*64 + c0 + 1)*HW + pix] = v1;
    g_pre[((size_t)b*64 + c0 + 2)*HW + pix] = v2;
    g_pre[((size_t)b*64 + c0 + 3)*HW + pix] = v3;
    g_pre[((size_t)b*64 + c0 + 4)*HW + pix] = v4;
    g_pre[((size_t)b*64 + c0 + 5)*HW + pix] = v5;
    g_pre[((size_t)b*64 + c0 + 6)*HW + pix] = v6;
    g_pre[((size_t)b*64 + c0 + 7)*HW + pix] = v7;
    float s0 = v0+v1, q0 = fmaf(v0,v0, v1*v1);
    float s1 = v2+v3, q1 = fmaf(v2,v2, v3*v3);
    float s2 = v4+v5, q2 = fmaf(v4,v4, v5*v5);
    float s3 = v6+v7, q3 = fmaf(v6,v6, v7*v7);
#pragma unroll
    for (int o = 16; o > 0; o >>= 1) {
        s0 += __shfl_xor_sync(0xFFFFFFFF, s0, o);
        q0 += __shfl_xor_sync(0xFFFFFFFF, q0, o);
        s1 += __shfl_xor_sync(0xFFFFFFFF, s1, o);
        q1 += __shfl_xor_sync(0xFFFFFFFF, q1, o);
        s2 += __shfl_xor_sync(0xFFFFFFFF, s2, o);
        q2 += __shfl_xor_sync(0xFFFFFFFF, q2, o);
        s3 += __shfl_xor_sync(0xFFFFFFFF, s3, o);
        q3 += __shfl_xor_sync(0xFFFFFFFF, q3, o);
    }
    if ((tid & 31) == 0) {
        int wslot = (tid >> 5) & 1;
        float2* dst = &g_part[((size_t)blk*2 + wslot)*32 + 4*cg];
        dst[0] = make_float2(s0, q0);
        dst[1] = make_float2(s1, q1);
        dst[2] = make_float2(s2, q2);
        dst[3] = make_float2(s3, q3);
    }
}

// ---------------------------------------------------------------------------
// Kernel 4a: final stats: reduce warp-partials per (b,group).
// ---------------------------------------------------------------------------
__global__ __launch_bounds__(256) void k4a_final()
{
    __shared__ float2 sp[256];
    const int bg = blockIdx.x;              // 0..127
    const int b = bg >> 5, g = bg & 31;
    float s = 0.f, q = 0.f;
    for (int j = threadIdx.x; j < 512; j += 256) {
        float2 v = g_part[(size_t)(b*512 + j)*32 + g];
        s += v.x; q += v.y;
    }
    sp[threadIdx.x] = make_float2(s, q);
    __syncthreads();
    for (int st = 128; st > 0; st >>= 1) {
        if (threadIdx.x < st) {
            sp[threadIdx.x].x += sp[threadIdx.x + st].x;
            sp[threadIdx.x].y += sp[threadIdx.x + st].y;
        }
        __syncthreads();
    }
    if (threadIdx.x == 0) {
        float mean = sp[0].x * (1.f/32768.f);
        float var  = sp[0].y * (1.f/32768.f) - mean*mean;
        g_stats[bg*2]   = mean;
        g_stats[bg*2+1] = rsqrtf(var + 1e-5f);
    }
}

// ---------------------------------------------------------------------------
// Kernel 4b: normalize + affine + exact GELU (float4)
// ---------------------------------------------------------------------------
__global__ __launch_bounds__(256) void k4b_norm(
    const float* __restrict__ gamma,
    const float* __restrict__ beta,
    float* __restrict__ out)
{
    const int i4 = blockIdx.x * 256 + threadIdx.x;
    const int i  = i4 << 2;
    const int c  = (i >> 14) & 63;
    const int b  = i >> 20;
    const int bg = b*32 + (c >> 1);
    const float mean = g_stats[bg*2];
    const float rstd = g_stats[bg*2 + 1];
    const float ga = __ldg(gamma + c), be = __ldg(beta + c);
    float4 v = ((const float4*)g_pre)[i4];
    float4 r;
    float yv;
    yv = (v.x - mean) * rstd * ga + be;
    r.x = 0.5f * yv * (1.f + erff(yv * 0.70710678118654752f));
    yv = (v.y - mean) * rstd * ga + be;
    r.y = 0.5f * yv * (1.f + erff(yv * 0.70710678118654752f));
    yv = (v.z - mean) * rstd * ga + be;
    r.z = 0.5f * yv * (1.f + erff(yv * 0.70710678118654752f));
    yv = (v.w - mean) * rstd * ga + be;
    r.w = 0.5f * yv * (1.f + erff(yv * 0.70710678118654752f));
    ((float4*)out)[i4] = r;
}

// ---------------------------------------------------------------------------
extern "C" void kernel_launch(void* const* d_in, const int* in_sizes, int n_in,
                              void* d_out, int out_size)
{
    const float* x       = (const float*)d_in[0];
    const float* w_off1  = (const float*)d_in[1];
    const float* w_off2  = (const float*)d_in[2];
    const float* w_mask1 = (const float*)d_in[3];
    const float* w_mask2 = (const float*)d_in[4];
    const float* weight  = (const float*)d_in[5];
    const float* bias    = (const float*)d_in[6];
    const float* gamma   = (const float*)d_in[7];
    const float* beta    = (const float*)d_in[8];
    float* out = (float*)d_out;

    cudaFuncSetAttribute(k1_wmma, cudaFuncAttributeMaxDynamicSharedMemorySize, K1_SMEM);
    cudaFuncSetAttribute(k2_wmma, cudaFuncAttributeMaxDynamicSharedMemorySize, K2_SMEM);

    k0_prep <<<64, 256>>>(w_off1, w_mask1, w_off2, w_mask2);
    k1_wmma <<<512, 256, K1_SMEM>>>(x);
    k2_wmma <<<dim3(512, 2), 256, K2_SMEM>>>();
    k3_sample<<<1024, 512>>>(weight, bias);
    k4a_final<<<128, 256>>>();
    k4b_norm<<<4096, 256>>>(gamma, beta, out);
}

// round 10
// speedup vs baseline: 3.0579x; 1.0395x over previous
#include <cuda_runtime.h>
#include <cuda_fp16.h>
#include <mma.h>
#include <math.h>
#include <stdint.h>

using namespace nvcuda;

#define Bdim 4
#define Cdim 64
#define Hdim 128
#define Wdim 128
#define HW (Hdim*Wdim)

#define PADH 72            // halfs per smem row for B tiles (144 B)

// ---------------------------------------------------------------------------
// Device scratch
// ---------------------------------------------------------------------------
__device__ uint4 t1Th[Bdim*HW*8];       // half [pix][64ch] (offset path)
__device__ uint4 t2Th[Bdim*HW*8];       // half [pix][64ch] (mask path)
__device__ uint4 g_x8[Bdim*8*HW];       // half x, channel-oct packed: [b][c8][pix]
__device__ uint4 wB1h[1024];            // half [128 cout][64 cin]  (w_off1 | w_mask1)
__device__ uint4 wB2o[2304];            // half [9 tap][32 cout][64 cin] (w_off2, rows 18-31 zero)
__device__ uint4 wB2m[2304];            // half [9 tap][32 cout][64 cin] (w_mask2, rows 9-31 zero)
__device__ float g_off [Bdim*18*HW];
__device__ float g_mask[Bdim*9*HW];
__device__ float g_pre [Bdim*Cdim*HW];
__device__ float2 g_part[2048*32];      // per-warp-slot per-group partial (sum, sumsq)
__device__ float g_stats[256];

// ---------------------------------------------------------------------------
// Kernel 0: weight prep -> half, GEMM-friendly layouts
// ---------------------------------------------------------------------------
__global__ __launch_bounds__(256) void k0_prep(
    const float* __restrict__ w_off1, const float* __restrict__ w_mask1,
    const float* __restrict__ w_off2, const float* __restrict__ w_mask2)
{
    __half* b1  = (__half*)wB1h;
    __half* b2o = (__half*)wB2o;
    __half* b2m = (__half*)wB2m;
    for (int j = blockIdx.x * 256 + threadIdx.x; j < 45056; j += gridDim.x * 256) {
        if (j < 8192) {
            int o = j >> 6, c = j & 63;
            float v = (o < 64) ? w_off1[o*64 + c] : w_mask1[(o-64)*64 + c];
            b1[j] = __float2half_rn(v);
        } else if (j < 26624) {
            int j2 = j - 8192;
            int t = j2 >> 11, o = (j2 >> 6) & 31, c = j2 & 63;
            float v = (o < 18) ? w_off2[o*576 + c*9 + t] : 0.f;
            b2o[j2] = __float2half_rn(v);
        } else {
            int j2 = j - 26624;
            int t = j2 >> 11, o = (j2 >> 6) & 31, c = j2 & 63;
            float v = (o < 9) ? w_mask2[o*576 + c*9 + t] : 0.f;
            b2m[j2] = __float2half_rn(v);
        }
    }
}

// ---------------------------------------------------------------------------
// Kernel 1: both 1x1 convs as one wmma GEMM; also emits g_x8 (oct-packed x).
// Two 4-accumulator MMA halves -> small staging (35KB) -> 3 CTAs/SM.
// ---------------------------------------------------------------------------
#define K1_A    0
#define K1_B    18432                  // 128*144
#define K1_STG  36864
#define K1_SMEM (36864 + 34816)        // staging 8 warps * 16 rows * 68 f32 = 71680 B

__global__ __launch_bounds__(256, 3) void k1_wmma(const float* __restrict__ x)
{
    extern __shared__ char sm[];
    __half* Ah = (__half*)(sm + K1_A);
    __half* Bh = (__half*)(sm + K1_B);
    float*  Sg = (float*) (sm + K1_STG);
    const int tid = threadIdx.x;
    const int wid = tid >> 5, lid = tid & 31;
    const int p0  = blockIdx.x * 128;
    const int b   = p0 >> 14;
    const int pi  = p0 & 16383;

    for (int j = tid; j < 1024; j += 256) {
        int o = j >> 3, seg = j & 7;
        *(uint4*)((char*)Bh + o*144 + seg*16) = wB1h[j];
    }
    const float* xb = x + (size_t)b * 64 * HW + pi;
    for (int j = tid; j < 4096; j += 256) {
        int cp = j >> 7, p = j & 127;
        float va = xb[(2*cp  )*HW + p];
        float vb = xb[(2*cp+1)*HW + p];
        __half2 h = __floats2half2_rn(va, vb);
        *(uint32_t*)((char*)Ah + p*144 + cp*4) = *(uint32_t*)&h;
    }
    __syncthreads();

    // emit oct-packed x gather table: g_x8[(b*8+c8)*HW + pix]
    for (int j = tid; j < 1024; j += 256) {
        int c8 = j >> 7, p = j & 127;
        uint4 v = *(uint4*)((char*)Ah + p*144 + c8*16);
        g_x8[(size_t)((b*8 + c8) << 14) + pi + p] = v;
    }

    float* st = Sg + wid*16*68;
    for (int half = 0; half < 2; half++) {
        wmma::fragment<wmma::accumulator, 16, 16, 16, float> acc[4];
#pragma unroll
        for (int n = 0; n < 4; n++) wmma::fill_fragment(acc[n], 0.f);
#pragma unroll
        for (int k = 0; k < 4; k++) {
            wmma::fragment<wmma::matrix_a, 16, 16, 16, __half, wmma::row_major> fa;
            wmma::load_matrix_sync(fa, Ah + wid*16*PADH + k*16, PADH);
#pragma unroll
            for (int n = 0; n < 4; n++) {
                wmma::fragment<wmma::matrix_b, 16, 16, 16, __half, wmma::col_major> fb;
                wmma::load_matrix_sync(fb, Bh + (half*4 + n)*16*PADH + k*16, PADH);
                wmma::mma_sync(acc[n], fa, fb, acc[n]);
            }
        }
#pragma unroll
        for (int n = 0; n < 4; n++)
            wmma::store_matrix_sync(st + n*16, acc[n], 68, wmma::mem_row_major);
        __syncwarp();
#pragma unroll
        for (int i = 0; i < 4; i++) {
            int item  = i*32 + lid;          // 128 items: 16 rows x 8 chunks
            int row   = item >> 3;
            int chunk = item & 7;
            const float* s = st + row*68 + chunk*8;
            uint4 o4;
            __half2 h;
            h = __floats2half2_rn(s[0], s[1]); o4.x = *(uint32_t*)&h;
            h = __floats2half2_rn(s[2], s[3]); o4.y = *(uint32_t*)&h;
            h = __floats2half2_rn(s[4], s[5]); o4.z = *(uint32_t*)&h;
            h = __floats2half2_rn(s[6], s[7]); o4.w = *(uint32_t*)&h;
            int gp = p0 + wid*16 + row;
            if (half == 0) t1Th[(size_t)gp*8 + chunk] = o4;
            else           t2Th[(size_t)gp*8 + chunk] = o4;
        }
        __syncwarp();
    }
}

// ---------------------------------------------------------------------------
// Kernel 2: 3x3 convs via 3-row buffer + shifted wmma fragments.
// path 0 (offset): N=32 (2 frags). path 1 (mask): N=16 (1 frag; 9 couts real).
// ---------------------------------------------------------------------------
#define K2_AROW   10400                // halfs per dy row buffer (130*80)
#define K2_B      62400
#define K2_BSECT  4608                 // off path: 32 rows * 144B
#define K2_BSECTM 2304                 // mask path: 16 rows * 144B
#define K2_SMEM  (62400 + 9*4608)      // 103872 B

__global__ __launch_bounds__(256) void k2_wmma()
{
    extern __shared__ char sm[];
    __half* Ah = (__half*)sm;
    __half* Bh = (__half*)(sm + K2_B);
    float*  Sg = (float*)sm;             // overlay on A after MMA phase
    const int tid = threadIdx.x;
    const int wid = tid >> 5, lid = tid & 31;
    const int bx = blockIdx.x;
    const int b = bx >> 7, y = bx & 127;
    const int path = blockIdx.y;

    if (path == 0) {
        for (int j = tid; j < 2304; j += 256) {
            int t = j >> 8, o = (j >> 3) & 31, seg = j & 7;
            *(uint4*)((char*)Bh + t*K2_BSECT + o*144 + seg*16) = wB2o[j];
        }
    } else {
        for (int j = tid; j < 1152; j += 256) {
            int t = j >> 7, o = (j >> 3) & 15, seg = j & 7;
            *(uint4*)((char*)Bh + t*K2_BSECTM + o*144 + seg*16) = wB2m[t*256 + o*8 + seg];
        }
    }
    const uint4* src = path ? t2Th : t1Th;
    const uint4 z4 = make_uint4(0u,0u,0u,0u);
    for (int j = tid; j < 3120; j += 256) {       // 3 dy * 130 pix * 8 seg
        int dy = j / 1040;
        int r  = j - dy*1040;
        int p  = r >> 3, seg = r & 7;
        int yy = y + dy - 1;
        int px = p - 1;
        uint4 v = z4;
        if ((unsigned)yy < 128u && (unsigned)px < 128u)
            v = src[(size_t)((b << 14) + (yy << 7) + px) * 8 + seg];
        *(uint4*)((char*)Ah + dy*20800 + p*160 + seg*16) = v;
    }
    __syncthreads();

    if (path == 0) {
        wmma::fragment<wmma::accumulator, 16, 16, 16, float> acc[2];
        wmma::fill_fragment(acc[0], 0.f);
        wmma::fill_fragment(acc[1], 0.f);
        for (int dy = 0; dy < 3; dy++) {
            const __half* Ad = Ah + dy*K2_AROW + wid*16*80;
#pragma unroll
            for (int dx = 0; dx < 3; dx++) {
                const __half* Adx = Ad + dx*80;
                const __half* Bt  = Bh + (dy*3 + dx)*(K2_BSECT/2);
#pragma unroll
                for (int k = 0; k < 4; k++) {
                    wmma::fragment<wmma::matrix_a, 16, 16, 16, __half, wmma::row_major> fa;
                    wmma::load_matrix_sync(fa, Adx + k*16, 80);
#pragma unroll
                    for (int n = 0; n < 2; n++) {
                        wmma::fragment<wmma::matrix_b, 16, 16, 16, __half, wmma::col_major> fb;
                        wmma::load_matrix_sync(fb, Bt + n*16*PADH + k*16, PADH);
                        wmma::mma_sync(acc[n], fa, fb, acc[n]);
                    }
                }
            }
        }
        __syncthreads();
        float* st = Sg + wid*16*36;
        wmma::store_matrix_sync(st,      acc[0], 36, wmma::mem_row_major);
        wmma::store_matrix_sync(st + 16, acc[1], 36, wmma::mem_row_major);
        __syncwarp();
        const int p_ = lid & 15;
        const int oh = lid >> 4;
        const int pix = y*Wdim + wid*16 + p_;
#pragma unroll
        for (int j = 0; j < 9; j++) {
            int o = oh*9 + j;
            g_off[((size_t)b*18 + o)*HW + pix] = st[p_*36 + o];
        }
    } else {
        wmma::fragment<wmma::accumulator, 16, 16, 16, float> acc;
        wmma::fill_fragment(acc, 0.f);
        for (int dy = 0; dy < 3; dy++) {
            const __half* Ad = Ah + dy*K2_AROW + wid*16*80;
#pragma unroll
            for (int dx = 0; dx < 3; dx++) {
                const __half* Adx = Ad + dx*80;
                const __half* Bt  = Bh + (dy*3 + dx)*(K2_BSECTM/2);
#pragma unroll
                for (int k = 0; k < 4; k++) {
                    wmma::fragment<wmma::matrix_a, 16, 16, 16, __half, wmma::row_major> fa;
                    wmma::load_matrix_sync(fa, Adx + k*16, 80);
                    wmma::fragment<wmma::matrix_b, 16, 16, 16, __half, wmma::col_major> fb;
                    wmma::load_matrix_sync(fb, Bt + k*16, PADH);
                    wmma::mma_sync(acc, fa, fb, acc);
                }
            }
        }
        __syncthreads();
        float* st = Sg + wid*16*36;
        wmma::store_matrix_sync(st, acc, 36, wmma::mem_row_major);
        __syncwarp();
        const int p_ = lid & 15;
        const int oh = lid >> 4;
        const int pix = y*Wdim + wid*16 + p_;
        if (oh == 0) {
#pragma unroll
            for (int j = 0; j < 9; j++) {
                float v = st[p_*36 + j];
                g_mask[((size_t)b*9 + j)*HW + pix] = 1.f / (1.f + expf(-v));
            }
        }
    }
}

// ---------------------------------------------------------------------------
// Kernel 3: deformable gather (8-channel LDG.128) + einsum + bias.
// INLINE per-tap coefficient recompute (no sI/sC smem -> no LDS crossbar
// share, no phase-1 barrier). Block = 64 pixels x 512 threads (8 ch-octs).
// Fused GN partials.
// ---------------------------------------------------------------------------
__global__ __launch_bounds__(512) void k3_sample(
    const float* __restrict__ wgt,
    const float* __restrict__ bias)
{
    __shared__ float4 sw8[9*8*2];       // [k][cg] weight oct (2x float4)
    __shared__ float  sb[64];

    const int tid = threadIdx.x;
    if (tid < 144) {
        int k = tid / 16, idx = tid & 15;
        int cg = idx >> 1, h = idx & 1;
        int c0 = cg*8 + h*4;
        sw8[(k*8 + cg)*2 + h] = make_float4(wgt[(c0  )*9 + k], wgt[(c0+1)*9 + k],
                                            wgt[(c0+2)*9 + k], wgt[(c0+3)*9 + k]);
    }
    if (tid >= 448) sb[tid - 448] = bias[tid - 448];
    __syncthreads();

    const int blk = blockIdx.x;             // 1024
    const int b   = blk >> 8;               // 256 blocks per batch
    const int p0  = (blk & 255) * 64;       // pixel within image
    const int p   = tid & 63;
    const int cg  = tid >> 6;               // 0..7 -> channels cg*8..cg*8+7
    const int pix = p0 + p;
    const int gy  = pix >> 7, gx = pix & 127;
    const uint4*  x8   = g_x8  + (size_t)((b*8 + cg) << 14);
    const float*  offb = g_off + (size_t)b * 18 * HW + pix;
    const float*  mkb  = g_mask + (size_t)b * 9 * HW + pix;

    float a0=0.f,a1=0.f,a2=0.f,a3=0.f,a4=0.f,a5=0.f,a6=0.f,a7=0.f;

#pragma unroll
    for (int k = 0; k < 9; k++) {
        // inline tap record (coalesced 4B reads, pure ALU after)
        float oy = __ldg(offb + (2*k  )*HW);
        float ox = __ldg(offb + (2*k+1)*HW);
        float mk = __ldg(mkb  +  k     *HW);
        float py  = oy + (float)(gy + k/3 - 1);
        float pxx = ox + (float)(gx + k%3 - 1);
        float y0f = floorf(py),  x0f = floorf(pxx);
        float wy1 = py - y0f,    wx1 = pxx - x0f;
        int   y0  = (int)y0f,    xx0 = (int)x0f;
        int cy0 = min(max(y0,   0), Hdim-1), cy1 = min(max(y0+1, 0), Hdim-1);
        int cx0 = min(max(xx0,  0), Wdim-1), cx1 = min(max(xx0+1,0), Wdim-1);
        int ibase = cy0*Wdim + cx0;
        int dxx   = cx1 - cx0;
        int dyW   = (cy1 - cy0)*Wdim;
        float vy0 = (y0   >= 0 && y0   < Hdim) ? 1.f : 0.f;
        float vy1 = (y0+1 >= 0 && y0+1 < Hdim) ? 1.f : 0.f;
        float vx0 = (xx0  >= 0 && xx0  < Wdim) ? 1.f : 0.f;
        float vx1 = (xx0+1>= 0 && xx0+1< Wdim) ? 1.f : 0.f;
        float ay0 = (1.f - wy1) * vy0 * mk;
        float ay1 = wy1 * vy1 * mk;
        float ax0 = (1.f - wx1) * vx0;
        float ax1 = wx1 * vx1;
        float4 C = make_float4(ay0*ax0, ay0*ax1, ay1*ax0, ay1*ax1);

        float4 Wa = sw8[(k*8 + cg)*2];
        float4 Wb = sw8[(k*8 + cg)*2 + 1];
        uint4 u00 = __ldg(x8 + ibase);
        uint4 u01 = __ldg(x8 + ibase + dxx);
        uint4 u10 = __ldg(x8 + ibase + dyW);
        uint4 u11 = __ldg(x8 + ibase + dyW + dxx);
        float2 f00, f01, f10, f11;
        float s;
        // ch 0,1
        f00 = __half22float2(*(__half2*)&u00.x); f01 = __half22float2(*(__half2*)&u01.x);
        f10 = __half22float2(*(__half2*)&u10.x); f11 = __half22float2(*(__half2*)&u11.x);
        s = C.x*f00.x; s = fmaf(C.y,f01.x,s); s = fmaf(C.z,f10.x,s); s = fmaf(C.w,f11.x,s); a0 = fmaf(Wa.x, s, a0);
        s = C.x*f00.y; s = fmaf(C.y,f01.y,s); s = fmaf(C.z,f10.y,s); s = fmaf(C.w,f11.y,s); a1 = fmaf(Wa.y, s, a1);
        // ch 2,3
        f00 = __half22float2(*(__half2*)&u00.y); f01 = __half22float2(*(__half2*)&u01.y);
        f10 = __half22float2(*(__half2*)&u10.y); f11 = __half22float2(*(__half2*)&u11.y);
        s = C.x*f00.x; s = fmaf(C.y,f01.x,s); s = fmaf(C.z,f10.x,s); s = fmaf(C.w,f11.x,s); a2 = fmaf(Wa.z, s, a2);
        s = C.x*f00.y; s = fmaf(C.y,f01.y,s); s = fmaf(C.z,f10.y,s); s = fmaf(C.w,f11.y,s); a3 = fmaf(Wa.w, s, a3);
        // ch 4,5
        f00 = __half22float2(*(__half2*)&u00.z); f01 = __half22float2(*(__half2*)&u01.z);
        f10 = __half22float2(*(__half2*)&u10.z); f11 = __half22float2(*(__half2*)&u11.z);
        s = C.x*f00.x; s = fmaf(C.y,f01.x,s); s = fmaf(C.z,f10.x,s); s = fmaf(C.w,f11.x,s); a4 = fmaf(Wb.x, s, a4);
        s = C.x*f00.y; s = fmaf(C.y,f01.y,s); s = fmaf(C.z,f10.y,s); s = fmaf(C.w,f11.y,s); a5 = fmaf(Wb.y, s, a5);
        // ch 6,7
        f00 = __half22float2(*(__half2*)&u00.w); f01 = __half22float2(*(__half2*)&u01.w);
        f10 = __half22float2(*(__half2*)&u10.w); f11 = __half22float2(*(__half2*)&u11.w);
        s = C.x*f00.x; s = fmaf(C.y,f01.x,s); s = fmaf(C.z,f10.x,s); s = fmaf(C.w,f11.x,s); a6 = fmaf(Wb.z, s, a6);
        s = C.x*f00.y; s = fmaf(C.y,f01.y,s); s = fmaf(C.z,f10.y,s); s = fmaf(C.w,f11.y,s); a7 = fmaf(Wb.w, s, a7);
    }

    // write + groupnorm partials (channels 8cg..8cg+7 = groups 4cg..4cg+3)
    const int c0 = cg*8;
    float v0 = a0 + sb[c0  ], v1 = a1 + sb[c0+1];
    float v2 = a2 + sb[c0+2], v3 = a3 + sb[c0+3];
    float v4 = a4 + sb[c0+4], v5 = a5 + sb[c0+5];
    float v6 = a6 + sb[c0+6], v7 = a7 + sb[c0+7];
    g_pre[((size_t)b*64 + c0    )*HW + pix] = v0;
    g_pre[((size_t)b*64 + c0 + 1)*HW + pix] = v1;
    g_pre[((size_t)b*64 + c0 + 2)*HW + pix] = v2;
    g_pre[((size_t)b*64 + c0 + 3)*HW + pix] = v3;
    g_pre[((size_t)b*64 + c0 + 4)*HW + pix] = v4;
    g_pre[((size_t)b*64 + c0 + 5)*HW + pix] = v5;
    g_pre[((size_t)b*64 + c0 + 6)*HW + pix] = v6;
    g_pre[((size_t)b*64 + c0 + 7)*HW + pix] = v7;
    float s0 = v0+v1, q0 = fmaf(v0,v0, v1*v1);
    float s1 = v2+v3, q1 = fmaf(v2,v2, v3*v3);
    float s2 = v4+v5, q2 = fmaf(v4,v4, v5*v5);
    float s3 = v6+v7, q3 = fmaf(v6,v6, v7*v7);
#pragma unroll
    for (int o = 16; o > 0; o >>= 1) {
        s0 += __shfl_xor_sync(0xFFFFFFFF, s0, o);
        q0 += __shfl_xor_sync(0xFFFFFFFF, q0, o);
        s1 += __shfl_xor_sync(0xFFFFFFFF, s1, o);
        q1 += __shfl_xor_sync(0xFFFFFFFF, q1, o);
        s2 += __shfl_xor_sync(0xFFFFFFFF, s2, o);
        q2 += __shfl_xor_sync(0xFFFFFFFF, q2, o);
        s3 += __shfl_xor_sync(0xFFFFFFFF, s3, o);
        q3 += __shfl_xor_sync(0xFFFFFFFF, q3, o);
    }
    if ((tid & 31) == 0) {
        int wslot = (tid >> 5) & 1;
        float2* dst = &g_part[((size_t)blk*2 + wslot)*32 + 4*cg];
        dst[0] = make_float2(s0, q0);
        dst[1] = make_float2(s1, q1);
        dst[2] = make_float2(s2, q2);
        dst[3] = make_float2(s3, q3);
    }
}

// ---------------------------------------------------------------------------
// Kernel 4a: final stats: reduce warp-partials per (b,group).
// ---------------------------------------------------------------------------
__global__ __launch_bounds__(256) void k4a_final()
{
    __shared__ float2 sp[256];
    const int bg = blockIdx.x;              // 0..127
    const int b = bg >> 5, g = bg & 31;
    float s = 0.f, q = 0.f;
    for (int j = threadIdx.x; j < 512; j += 256) {
        float2 v = g_part[(size_t)(b*512 + j)*32 + g];
        s += v.x; q += v.y;
    }
    sp[threadIdx.x] = make_float2(s, q);
    __syncthreads();
    for (int st = 128; st > 0; st >>= 1) {
        if (threadIdx.x < st) {
            sp[threadIdx.x].x += sp[threadIdx.x + st].x;
            sp[threadIdx.x].y += sp[threadIdx.x + st].y;
        }
        __syncthreads();
    }
    if (threadIdx.x == 0) {
        float mean = sp[0].x * (1.f/32768.f);
        float var  = sp[0].y * (1.f/32768.f) - mean*mean;
        g_stats[bg*2]   = mean;
        g_stats[bg*2+1] = rsqrtf(var + 1e-5f);
    }
}

// ---------------------------------------------------------------------------
// Kernel 4b: normalize + affine + exact GELU (float4)
// ---------------------------------------------------------------------------
__global__ __launch_bounds__(256) void k4b_norm(
    const float* __restrict__ gamma,
    const float* __restrict__ beta,
    float* __restrict__ out)
{
    const int i4 = blockIdx.x * 256 + threadIdx.x;
    const int i  = i4 << 2;
    const int c  = (i >> 14) & 63;
    const int b  = i >> 20;
    const int bg = b*32 + (c >> 1);
    const float mean = g_stats[bg*2];
    const float rstd = g_stats[bg*2 + 1];
    const float ga = __ldg(gamma + c), be = __ldg(beta + c);
    float4 v = ((const float4*)g_pre)[i4];
    float4 r;
    float yv;
    yv = (v.x - mean) * rstd * ga + be;
    r.x = 0.5f * yv * (1.f + erff(yv * 0.70710678118654752f));
    yv = (v.y - mean) * rstd * ga + be;
    r.y = 0.5f * yv * (1.f + erff(yv * 0.70710678118654752f));
    yv = (v.z - mean) * rstd * ga + be;
    r.z = 0.5f * yv * (1.f + erff(yv * 0.70710678118654752f));
    yv = (v.w - mean) * rstd * ga + be;
    r.w = 0.5f * yv * (1.f + erff(yv * 0.70710678118654752f));
    ((float4*)out)[i4] = r;
}

// ---------------------------------------------------------------------------
extern "C" void kernel_launch(void* const* d_in, const int* in_sizes, int n_in,
                              void* d_out, int out_size)
{
    const float* x       = (const float*)d_in[0];
    const float* w_off1  = (const float*)d_in[1];
    const float* w_off2  = (const float*)d_in[2];
    const float* w_mask1 = (const float*)d_in[3];
    const float* w_mask2 = (const float*)d_in[4];
    const float* weight  = (const float*)d_in[5];
    const float* bias    = (const float*)d_in[6];
    const float* gamma   = (const float*)d_in[7];
    const float* beta    = (const float*)d_in[8];
    float* out = (float*)d_out;

    cudaFuncSetAttribute(k1_wmma, cudaFuncAttributeMaxDynamicSharedMemorySize, K1_SMEM);
    cudaFuncSetAttribute(k2_wmma, cudaFuncAttributeMaxDynamicSharedMemorySize, K2_SMEM);

    k0_prep <<<64, 256>>>(w_off1, w_mask1, w_off2, w_mask2);
    k1_wmma <<<512, 256, K1_SMEM>>>(x);
    k2_wmma <<<dim3(512, 2), 256, K2_SMEM>>>();
    k3_sample<<<1024, 512>>>(weight, bias);
    k4a_final<<<128, 256>>>();
    k4b_norm<<<4096, 256>>>(gamma, beta, out);
}

// round 11
// speedup vs baseline: 3.0747x; 1.0055x over previous
#include <cuda_runtime.h>
#include <cuda_fp16.h>
#include <mma.h>
#include <math.h>
#include <stdint.h>

using namespace nvcuda;

#define Bdim 4
#define Cdim 64
#define Hdim 128
#define Wdim 128
#define HW (Hdim*Wdim)

#define PADH 72            // halfs per smem row for B tiles (144 B)

// ---------------------------------------------------------------------------
// Device scratch
// ---------------------------------------------------------------------------
__device__ uint4 t1Th[Bdim*HW*8];       // half [pix][64ch] (offset path)
__device__ uint4 t2Th[Bdim*HW*8];       // half [pix][64ch] (mask path)
__device__ uint4 g_x8[Bdim*8*HW];       // half x, channel-oct packed: [b][c8][pix]
__device__ uint4 wB1h[1024];            // half [128 cout][64 cin]  (w_off1 | w_mask1)
__device__ uint4 wB2o[2304];            // half [9 tap][32 cout][64 cin] (w_off2, rows 18-31 zero)
__device__ uint4 wB2m[2304];            // half [9 tap][32 cout][64 cin] (w_mask2, rows 9-31 zero)
__device__ float g_off [Bdim*18*HW];
__device__ float g_mask[Bdim*9*HW];
__device__ float g_pre [Bdim*Cdim*HW];
__device__ float2 g_part[2048*32];      // per-warp-slot per-group partial (sum, sumsq)
__device__ float g_stats[256];

// ---------------------------------------------------------------------------
// Kernel 0: weight prep -> half, GEMM-friendly layouts
// ---------------------------------------------------------------------------
__global__ __launch_bounds__(256) void k0_prep(
    const float* __restrict__ w_off1, const float* __restrict__ w_mask1,
    const float* __restrict__ w_off2, const float* __restrict__ w_mask2)
{
    __half* b1  = (__half*)wB1h;
    __half* b2o = (__half*)wB2o;
    __half* b2m = (__half*)wB2m;
    for (int j = blockIdx.x * 256 + threadIdx.x; j < 45056; j += gridDim.x * 256) {
        if (j < 8192) {
            int o = j >> 6, c = j & 63;
            float v = (o < 64) ? w_off1[o*64 + c] : w_mask1[(o-64)*64 + c];
            b1[j] = __float2half_rn(v);
        } else if (j < 26624) {
            int j2 = j - 8192;
            int t = j2 >> 11, o = (j2 >> 6) & 31, c = j2 & 63;
            float v = (o < 18) ? w_off2[o*576 + c*9 + t] : 0.f;
            b2o[j2] = __float2half_rn(v);
        } else {
            int j2 = j - 26624;
            int t = j2 >> 11, o = (j2 >> 6) & 31, c = j2 & 63;
            float v = (o < 9) ? w_mask2[o*576 + c*9 + t] : 0.f;
            b2m[j2] = __float2half_rn(v);
        }
    }
}

// ---------------------------------------------------------------------------
// Kernel 1: both 1x1 convs as one wmma GEMM; also emits g_x8 (oct-packed x).
// Two 4-accumulator MMA halves -> small staging (35KB) -> 3 CTAs/SM.
// ---------------------------------------------------------------------------
#define K1_A    0
#define K1_B    18432                  // 128*144
#define K1_STG  36864
#define K1_SMEM (36864 + 34816)        // 71680 B

__global__ __launch_bounds__(256, 3) void k1_wmma(const float* __restrict__ x)
{
    extern __shared__ char sm[];
    __half* Ah = (__half*)(sm + K1_A);
    __half* Bh = (__half*)(sm + K1_B);
    float*  Sg = (float*) (sm + K1_STG);
    const int tid = threadIdx.x;
    const int wid = tid >> 5, lid = tid & 31;
    const int p0  = blockIdx.x * 128;
    const int b   = p0 >> 14;
    const int pi  = p0 & 16383;

    for (int j = tid; j < 1024; j += 256) {
        int o = j >> 3, seg = j & 7;
        *(uint4*)((char*)Bh + o*144 + seg*16) = wB1h[j];
    }
    const float* xb = x + (size_t)b * 64 * HW + pi;
    for (int j = tid; j < 4096; j += 256) {
        int cp = j >> 7, p = j & 127;
        float va = xb[(2*cp  )*HW + p];
        float vb = xb[(2*cp+1)*HW + p];
        __half2 h = __floats2half2_rn(va, vb);
        *(uint32_t*)((char*)Ah + p*144 + cp*4) = *(uint32_t*)&h;
    }
    __syncthreads();

    // emit oct-packed x gather table: g_x8[(b*8+c8)*HW + pix]
    for (int j = tid; j < 1024; j += 256) {
        int c8 = j >> 7, p = j & 127;
        uint4 v = *(uint4*)((char*)Ah + p*144 + c8*16);
        g_x8[(size_t)((b*8 + c8) << 14) + pi + p] = v;
    }

    float* st = Sg + wid*16*68;
    for (int half = 0; half < 2; half++) {
        wmma::fragment<wmma::accumulator, 16, 16, 16, float> acc[4];
#pragma unroll
        for (int n = 0; n < 4; n++) wmma::fill_fragment(acc[n], 0.f);
#pragma unroll
        for (int k = 0; k < 4; k++) {
            wmma::fragment<wmma::matrix_a, 16, 16, 16, __half, wmma::row_major> fa;
            wmma::load_matrix_sync(fa, Ah + wid*16*PADH + k*16, PADH);
#pragma unroll
            for (int n = 0; n < 4; n++) {
                wmma::fragment<wmma::matrix_b, 16, 16, 16, __half, wmma::col_major> fb;
                wmma::load_matrix_sync(fb, Bh + (half*4 + n)*16*PADH + k*16, PADH);
                wmma::mma_sync(acc[n], fa, fb, acc[n]);
            }
        }
#pragma unroll
        for (int n = 0; n < 4; n++)
            wmma::store_matrix_sync(st + n*16, acc[n], 68, wmma::mem_row_major);
        __syncwarp();
#pragma unroll
        for (int i = 0; i < 4; i++) {
            int item  = i*32 + lid;          // 128 items: 16 rows x 8 chunks
            int row   = item >> 3;
            int chunk = item & 7;
            const float* s = st + row*68 + chunk*8;
            uint4 o4;
            __half2 h;
            h = __floats2half2_rn(s[0], s[1]); o4.x = *(uint32_t*)&h;
            h = __floats2half2_rn(s[2], s[3]); o4.y = *(uint32_t*)&h;
            h = __floats2half2_rn(s[4], s[5]); o4.z = *(uint32_t*)&h;
            h = __floats2half2_rn(s[6], s[7]); o4.w = *(uint32_t*)&h;
            int gp = p0 + wid*16 + row;
            if (half == 0) t1Th[(size_t)gp*8 + chunk] = o4;
            else           t2Th[(size_t)gp*8 + chunk] = o4;
        }
        __syncwarp();
    }
}

// ---------------------------------------------------------------------------
// Kernel 2: 3x3 convs via 3-row buffer + shifted wmma fragments.
// path 0 (offset): N=32 (2 frags). path 1 (mask): N=16 (1 frag; 9 couts real).
// ---------------------------------------------------------------------------
#define K2_AROW   10400                // halfs per dy row buffer (130*80)
#define K2_B      62400
#define K2_BSECT  4608                 // off path: 32 rows * 144B
#define K2_BSECTM 2304                 // mask path: 16 rows * 144B
#define K2_SMEM  (62400 + 9*4608)      // 103872 B

__global__ __launch_bounds__(256) void k2_wmma()
{
    extern __shared__ char sm[];
    __half* Ah = (__half*)sm;
    __half* Bh = (__half*)(sm + K2_B);
    float*  Sg = (float*)sm;             // overlay on A after MMA phase
    const int tid = threadIdx.x;
    const int wid = tid >> 5, lid = tid & 31;
    const int bx = blockIdx.x;
    const int b = bx >> 7, y = bx & 127;
    const int path = blockIdx.y;

    if (path == 0) {
        for (int j = tid; j < 2304; j += 256) {
            int t = j >> 8, o = (j >> 3) & 31, seg = j & 7;
            *(uint4*)((char*)Bh + t*K2_BSECT + o*144 + seg*16) = wB2o[j];
        }
    } else {
        for (int j = tid; j < 1152; j += 256) {
            int t = j >> 7, o = (j >> 3) & 15, seg = j & 7;
            *(uint4*)((char*)Bh + t*K2_BSECTM + o*144 + seg*16) = wB2m[t*256 + o*8 + seg];
        }
    }
    const uint4* src = path ? t2Th : t1Th;
    const uint4 z4 = make_uint4(0u,0u,0u,0u);
    for (int j = tid; j < 3120; j += 256) {       // 3 dy * 130 pix * 8 seg
        int dy = j / 1040;
        int r  = j - dy*1040;
        int p  = r >> 3, seg = r & 7;
        int yy = y + dy - 1;
        int px = p - 1;
        uint4 v = z4;
        if ((unsigned)yy < 128u && (unsigned)px < 128u)
            v = src[(size_t)((b << 14) + (yy << 7) + px) * 8 + seg];
        *(uint4*)((char*)Ah + dy*20800 + p*160 + seg*16) = v;
    }
    __syncthreads();

    if (path == 0) {
        wmma::fragment<wmma::accumulator, 16, 16, 16, float> acc[2];
        wmma::fill_fragment(acc[0], 0.f);
        wmma::fill_fragment(acc[1], 0.f);
        for (int dy = 0; dy < 3; dy++) {
            const __half* Ad = Ah + dy*K2_AROW + wid*16*80;
#pragma unroll
            for (int dx = 0; dx < 3; dx++) {
                const __half* Adx = Ad + dx*80;
                const __half* Bt  = Bh + (dy*3 + dx)*(K2_BSECT/2);
#pragma unroll
                for (int k = 0; k < 4; k++) {
                    wmma::fragment<wmma::matrix_a, 16, 16, 16, __half, wmma::row_major> fa;
                    wmma::load_matrix_sync(fa, Adx + k*16, 80);
#pragma unroll
                    for (int n = 0; n < 2; n++) {
                        wmma::fragment<wmma::matrix_b, 16, 16, 16, __half, wmma::col_major> fb;
                        wmma::load_matrix_sync(fb, Bt + n*16*PADH + k*16, PADH);
                        wmma::mma_sync(acc[n], fa, fb, acc[n]);
                    }
                }
            }
        }
        __syncthreads();
        float* st = Sg + wid*16*36;
        wmma::store_matrix_sync(st,      acc[0], 36, wmma::mem_row_major);
        wmma::store_matrix_sync(st + 16, acc[1], 36, wmma::mem_row_major);
        __syncwarp();
        const int p_ = lid & 15;
        const int oh = lid >> 4;
        const int pix = y*Wdim + wid*16 + p_;
#pragma unroll
        for (int j = 0; j < 9; j++) {
            int o = oh*9 + j;
            g_off[((size_t)b*18 + o)*HW + pix] = st[p_*36 + o];
        }
    } else {
        wmma::fragment<wmma::accumulator, 16, 16, 16, float> acc;
        wmma::fill_fragment(acc, 0.f);
        for (int dy = 0; dy < 3; dy++) {
            const __half* Ad = Ah + dy*K2_AROW + wid*16*80;
#pragma unroll
            for (int dx = 0; dx < 3; dx++) {
                const __half* Adx = Ad + dx*80;
                const __half* Bt  = Bh + (dy*3 + dx)*(K2_BSECTM/2);
#pragma unroll
                for (int k = 0; k < 4; k++) {
                    wmma::fragment<wmma::matrix_a, 16, 16, 16, __half, wmma::row_major> fa;
                    wmma::load_matrix_sync(fa, Adx + k*16, 80);
                    wmma::fragment<wmma::matrix_b, 16, 16, 16, __half, wmma::col_major> fb;
                    wmma::load_matrix_sync(fb, Bt + k*16, PADH);
                    wmma::mma_sync(acc, fa, fb, acc);
                }
            }
        }
        __syncthreads();
        float* st = Sg + wid*16*36;
        wmma::store_matrix_sync(st, acc, 36, wmma::mem_row_major);
        __syncwarp();
        const int p_ = lid & 15;
        const int oh = lid >> 4;
        const int pix = y*Wdim + wid*16 + p_;
        if (oh == 0) {
#pragma unroll
            for (int j = 0; j < 9; j++) {
                float v = st[p_*36 + j];
                g_mask[((size_t)b*9 + j)*HW + pix] = 1.f / (1.f + expf(-v));
            }
        }
    }
}

// ---------------------------------------------------------------------------
// Kernel 3: deformable gather (8-channel LDG.128) + einsum + bias,
// fused groupnorm partials. Block = 64 pixels x 512 threads (8 ch-octs).
// Tap records built once in smem (phase 1), plain tap loop (R8 formulation:
// 52 regs -> 2 CTAs/SM).
// ---------------------------------------------------------------------------
__global__ __launch_bounds__(512) void k3_sample(
    const float* __restrict__ wgt,
    const float* __restrict__ bias)
{
    __shared__ float4 sw8[9*8*2];       // [k][cg] weight oct (2x float4)
    __shared__ float  sb[64];
    __shared__ int4   sI[9*64];
    __shared__ float4 sC[9*64];

    const int tid = threadIdx.x;
    if (tid < 144) {
        int k = tid / 16, idx = tid & 15;
        int cg = idx >> 1, h = idx & 1;
        int c0 = cg*8 + h*4;
        sw8[(k*8 + cg)*2 + h] = make_float4(wgt[(c0  )*9 + k], wgt[(c0+1)*9 + k],
                                            wgt[(c0+2)*9 + k], wgt[(c0+3)*9 + k]);
    }
    if (tid >= 448) sb[tid - 448] = bias[tid - 448];

    const int blk = blockIdx.x;             // 1024
    const int b   = blk >> 8;               // 256 blocks per batch
    const int p0  = (blk & 255) * 64;       // pixel within image

    for (int e = tid; e < 576; e += 512) {
        const int k = e >> 6;               // 0..8
        const int p = e & 63;
        const int pix = p0 + p;
        const int gy = pix >> 7, gx = pix & 127;
        const float* offb = g_off  + (size_t)b * 18 * HW;
        const float* mkb  = g_mask + (size_t)b * 9  * HW;
        float oy = offb[(2*k  )*HW + pix];
        float ox = offb[(2*k+1)*HW + pix];
        float mk = mkb [ k     *HW + pix];
        float py  = oy + (float)gy + (float)(k/3 - 1);
        float pxx = ox + (float)gx + (float)(k%3 - 1);
        float y0f = floorf(py),  x0f = floorf(pxx);
        float wy1 = py - y0f,    wx1 = pxx - x0f;
        int   y0  = (int)y0f,    xx0 = (int)x0f;
        int cy0 = min(max(y0,   0), Hdim-1), cy1 = min(max(y0+1, 0), Hdim-1);
        int cx0 = min(max(xx0,  0), Wdim-1), cx1 = min(max(xx0+1,0), Wdim-1);
        float vy0 = (y0   >= 0 && y0   < Hdim) ? 1.f : 0.f;
        float vy1 = (y0+1 >= 0 && y0+1 < Hdim) ? 1.f : 0.f;
        float vx0 = (xx0  >= 0 && xx0  < Wdim) ? 1.f : 0.f;
        float vx1 = (xx0+1>= 0 && xx0+1< Wdim) ? 1.f : 0.f;
        float ay0 = (1.f - wy1) * vy0 * mk;
        float ay1 = wy1 * vy1 * mk;
        float ax0 = (1.f - wx1) * vx0;
        float ax1 = wx1 * vx1;
        sI[k*64 + p] = make_int4(cy0*Wdim + cx0, cx1 - cx0, (cy1 - cy0)*Wdim, 0);
        sC[k*64 + p] = make_float4(ay0*ax0, ay0*ax1, ay1*ax0, ay1*ax1);
    }
    __syncthreads();

    const int p   = tid & 63;
    const int cg  = tid >> 6;               // 0..7 -> channels cg*8..cg*8+7
    const int pix = p0 + p;
    const uint4* x8 = g_x8 + (size_t)((b*8 + cg) << 14);

    float a0=0.f,a1=0.f,a2=0.f,a3=0.f,a4=0.f,a5=0.f,a6=0.f,a7=0.f;
    for (int k = 0; k < 9; k++) {
        int4   I  = sI[k*64 + p];
        float4 C  = sC[k*64 + p];
        float4 Wa = sw8[(k*8 + cg)*2];
        float4 Wb = sw8[(k*8 + cg)*2 + 1];
        uint4 u00 = __ldg(x8 + I.x);
        uint4 u01 = __ldg(x8 + I.x + I.y);
        uint4 u10 = __ldg(x8 + I.x + I.z);
        uint4 u11 = __ldg(x8 + I.x + I.z + I.y);
        float2 f00, f01, f10, f11;
        float s;
        // ch 0,1
        f00 = __half22float2(*(__half2*)&u00.x); f01 = __half22float2(*(__half2*)&u01.x);
        f10 = __half22float2(*(__half2*)&u10.x); f11 = __half22float2(*(__half2*)&u11.x);
        s = C.x*f00.x; s = fmaf(C.y,f01.x,s); s = fmaf(C.z,f10.x,s); s = fmaf(C.w,f11.x,s); a0 = fmaf(Wa.x, s, a0);
        s = C.x*f00.y; s = fmaf(C.y,f01.y,s); s = fmaf(C.z,f10.y,s); s = fmaf(C.w,f11.y,s); a1 = fmaf(Wa.y, s, a1);
        // ch 2,3
        f00 = __half22float2(*(__half2*)&u00.y); f01 = __half22float2(*(__half2*)&u01.y);
        f10 = __half22float2(*(__half2*)&u10.y); f11 = __half22float2(*(__half2*)&u11.y);
        s = C.x*f00.x; s = fmaf(C.y,f01.x,s); s = fmaf(C.z,f10.x,s); s = fmaf(C.w,f11.x,s); a2 = fmaf(Wa.z, s, a2);
        s = C.x*f00.y; s = fmaf(C.y,f01.y,s); s = fmaf(C.z,f10.y,s); s = fmaf(C.w,f11.y,s); a3 = fmaf(Wa.w, s, a3);
        // ch 4,5
        f00 = __half22float2(*(__half2*)&u00.z); f01 = __half22float2(*(__half2*)&u01.z);
        f10 = __half22float2(*(__half2*)&u10.z); f11 = __half22float2(*(__half2*)&u11.z);
        s = C.x*f00.x; s = fmaf(C.y,f01.x,s); s = fmaf(C.z,f10.x,s); s = fmaf(C.w,f11.x,s); a4 = fmaf(Wb.x, s, a4);
        s = C.x*f00.y; s = fmaf(C.y,f01.y,s); s = fmaf(C.z,f10.y,s); s = fmaf(C.w,f11.y,s); a5 = fmaf(Wb.y, s, a5);
        // ch 6,7
        f00 = __half22float2(*(__half2*)&u00.w); f01 = __half22float2(*(__half2*)&u01.w);
        f10 = __half22float2(*(__half2*)&u10.w); f11 = __half22float2(*(__half2*)&u11.w);
        s = C.x*f00.x; s = fmaf(C.y,f01.x,s); s = fmaf(C.z,f10.x,s); s = fmaf(C.w,f11.x,s); a6 = fmaf(Wb.z, s, a6);
        s = C.x*f00.y; s = fmaf(C.y,f01.y,s); s = fmaf(C.z,f10.y,s); s = fmaf(C.w,f11.y,s); a7 = fmaf(Wb.w, s, a7);
    }

    // write + groupnorm partials (channels 8cg..8cg+7 = groups 4cg..4cg+3)
    const int c0 = cg*8;
    float v0 = a0 + sb[c0  ], v1 = a1 + sb[c0+1];
    float v2 = a2 + sb[c0+2], v3 = a3 + sb[c0+3];
    float v4 = a4 + sb[c0+4], v5 = a5 + sb[c0+5];
    float v6 = a6 + sb[c0+6], v7 = a7 + sb[c0+7];
    g_pre[((size_t)b*64 + c0    )*HW + pix] = v0;
    g_pre[((size_t)b*64 + c0 + 1)*HW + pix] = v1;
    g_pre[((size_t)b*64 + c0 + 2)*HW + pix] = v2;
    g_pre[((size_t)b*64 + c0 + 3)*HW + pix] = v3;
    g_pre[((size_t)b*64 + c0 + 4)*HW + pix] = v4;
    g_pre[((size_t)b*64 + c0 + 5)*HW + pix] = v5;
    g_pre[((size_t)b*64 + c0 + 6)*HW + pix] = v6;
    g_pre[((size_t)b*64 + c0 + 7)*HW + pix] = v7;
    float s0 = v0+v1, q0 = fmaf(v0,v0, v1*v1);
    float s1 = v2+v3, q1 = fmaf(v2,v2, v3*v3);
    float s2 = v4+v5, q2 = fmaf(v4,v4, v5*v5);
    float s3 = v6+v7, q3 = fmaf(v6,v6, v7*v7);
#pragma unroll
    for (int o = 16; o > 0; o >>= 1) {
        s0 += __shfl_xor_sync(0xFFFFFFFF, s0, o);
        q0 += __shfl_xor_sync(0xFFFFFFFF, q0, o);
        s1 += __shfl_xor_sync(0xFFFFFFFF, s1, o);
        q1 += __shfl_xor_sync(0xFFFFFFFF, q1, o);
        s2 += __shfl_xor_sync(0xFFFFFFFF, s2, o);
        q2 += __shfl_xor_sync(0xFFFFFFFF, q2, o);
        s3 += __shfl_xor_sync(0xFFFFFFFF, s3, o);
        q3 += __shfl_xor_sync(0xFFFFFFFF, q3, o);
    }
    if ((tid & 31) == 0) {
        int wslot = (tid >> 5) & 1;
        float2* dst = &g_part[((size_t)blk*2 + wslot)*32 + 4*cg];
        dst[0] = make_float2(s0, q0);
        dst[1] = make_float2(s1, q1);
        dst[2] = make_float2(s2, q2);
        dst[3] = make_float2(s3, q3);
    }
}

// ---------------------------------------------------------------------------
// Kernel 4a: final stats: reduce warp-partials per (b,group).
// ---------------------------------------------------------------------------
__global__ __launch_bounds__(256) void k4a_final()
{
    __shared__ float2 sp[256];
    const int bg = blockIdx.x;              // 0..127
    const int b = bg >> 5, g = bg & 31;
    float s = 0.f, q = 0.f;
    for (int j = threadIdx.x; j < 512; j += 256) {
        float2 v = g_part[(size_t)(b*512 + j)*32 + g];
        s += v.x; q += v.y;
    }
    sp[threadIdx.x] = make_float2(s, q);
    __syncthreads();
    for (int st = 128; st > 0; st >>= 1) {
        if (threadIdx.x < st) {
            sp[threadIdx.x].x += sp[threadIdx.x + st].x;
            sp[threadIdx.x].y += sp[threadIdx.x + st].y;
        }
        __syncthreads();
    }
    if (threadIdx.x == 0) {
        float mean = sp[0].x * (1.f/32768.f);
        float var  = sp[0].y * (1.f/32768.f) - mean*mean;
        g_stats[bg*2]   = mean;
        g_stats[bg*2+1] = rsqrtf(var + 1e-5f);
    }
}

// ---------------------------------------------------------------------------
// Kernel 4b: normalize + affine + exact GELU (float4)
// ---------------------------------------------------------------------------
__global__ __launch_bounds__(256) void k4b_norm(
    const float* __restrict__ gamma,
    const float* __restrict__ beta,
    float* __restrict__ out)
{
    const int i4 = blockIdx.x * 256 + threadIdx.x;
    const int i  = i4 << 2;
    const int c  = (i >> 14) & 63;
    const int b  = i >> 20;
    const int bg = b*32 + (c >> 1);
    const float mean = g_stats[bg*2];
    const float rstd = g_stats[bg*2 + 1];
    const float ga = __ldg(gamma + c), be = __ldg(beta + c);
    float4 v = ((const float4*)g_pre)[i4];
    float4 r;
    float yv;
    yv = (v.x - mean) * rstd * ga + be;
    r.x = 0.5f * yv * (1.f + erff(yv * 0.70710678118654752f));
    yv = (v.y - mean) * rstd * ga + be;
    r.y = 0.5f * yv * (1.f + erff(yv * 0.70710678118654752f));
    yv = (v.z - mean) * rstd * ga + be;
    r.z = 0.5f * yv * (1.f + erff(yv * 0.70710678118654752f));
    yv = (v.w - mean) * rstd * ga + be;
    r.w = 0.5f * yv * (1.f + erff(yv * 0.70710678118654752f));
    ((float4*)out)[i4] = r;
}

// ---------------------------------------------------------------------------
extern "C" void kernel_launch(void* const* d_in, const int* in_sizes, int n_in,
                              void* d_out, int out_size)
{
    const float* x       = (const float*)d_in[0];
    const float* w_off1  = (const float*)d_in[1];
    const float* w_off2  = (const float*)d_in[2];
    const float* w_mask1 = (const float*)d_in[3];
    const float* w_mask2 = (const float*)d_in[4];
    const float* weight  = (const float*)d_in[5];
    const float* bias    = (const float*)d_in[6];
    const float* gamma   = (const float*)d_in[7];
    const float* beta    = (const float*)d_in[8];
    float* out = (float*)d_out;

    cudaFuncSetAttribute(k1_wmma, cudaFuncAttributeMaxDynamicSharedMemorySize, K1_SMEM);
    cudaFuncSetAttribute(k2_wmma, cudaFuncAttributeMaxDynamicSharedMemorySize, K2_SMEM);

    k0_prep <<<64, 256>>>(w_off1, w_mask1, w_off2, w_mask2);
    k1_wmma <<<512, 256, K1_SMEM>>>(x);
    k2_wmma <<<dim3(512, 2), 256, K2_SMEM>>>();
    k3_sample<<<1024, 512>>>(weight, bias);
    k4a_final<<<128, 256>>>();
    k4b_norm<<<4096, 256>>>(gamma, beta, out);
}

// round 14
// speedup vs baseline: 3.3685x; 1.0955x over previous
#include <cuda_runtime.h>
#include <cuda_fp16.h>
#include <mma.h>
#include <math.h>
#include <stdint.h>

using namespace nvcuda;

#define Bdim 4
#define Cdim 64
#define Hdim 128
#define Wdim 128
#define HW (Hdim*Wdim)

#define PADH 72            // halfs per smem row for B tiles (144 B)

// ---------------------------------------------------------------------------
// Device scratch
// ---------------------------------------------------------------------------
__device__ uint4 t1Th[Bdim*HW*8];       // half [pix][64ch] (offset path)
__device__ uint4 t2Th[Bdim*HW*8];       // half [pix][64ch] (mask path)
__device__ uint4 g_x8[Bdim*8*HW];       // half x, channel-oct packed: [b][c8][pix]
__device__ uint4 wB1h[1024];            // half [128 cout][64 cin]  (w_off1 | w_mask1)
__device__ uint4 wB2o[2304];            // half [9 tap][32 cout][64 cin] (w_off2, rows 18-31 zero)
__device__ uint4 wB2m[2304];            // half [9 tap][32 cout][64 cin] (w_mask2, rows 9-31 zero)
__device__ float g_off [Bdim*18*HW];
__device__ float g_mask[Bdim*9*HW];
__device__ float g_pre [Bdim*Cdim*HW];
__device__ float2 g_part[2048*32];      // per-warp-slot per-group partial (sum, sumsq)
__device__ float g_stats[256];

// ---------------------------------------------------------------------------
// Kernel 0: weight prep -> half, GEMM-friendly layouts
// ---------------------------------------------------------------------------
__global__ __launch_bounds__(256) void k0_prep(
    const float* __restrict__ w_off1, const float* __restrict__ w_mask1,
    const float* __restrict__ w_off2, const float* __restrict__ w_mask2)
{
    __half* b1  = (__half*)wB1h;
    __half* b2o = (__half*)wB2o;
    __half* b2m = (__half*)wB2m;
    for (int j = blockIdx.x * 256 + threadIdx.x; j < 45056; j += gridDim.x * 256) {
        if (j < 8192) {
            int o = j >> 6, c = j & 63;
            float v = (o < 64) ? w_off1[o*64 + c] : w_mask1[(o-64)*64 + c];
            b1[j] = __float2half_rn(v);
        } else if (j < 26624) {
            int j2 = j - 8192;
            int t = j2 >> 11, o = (j2 >> 6) & 31, c = j2 & 63;
            float v = (o < 18) ? w_off2[o*576 + c*9 + t] : 0.f;
            b2o[j2] = __float2half_rn(v);
        } else {
            int j2 = j - 26624;
            int t = j2 >> 11, o = (j2 >> 6) & 31, c = j2 & 63;
            float v = (o < 9) ? w_mask2[o*576 + c*9 + t] : 0.f;
            b2m[j2] = __float2half_rn(v);
        }
    }
}

// ---------------------------------------------------------------------------
// Kernel 1: both 1x1 convs as one wmma GEMM; also emits g_x8 (oct-packed x).
// Two 4-accumulator MMA halves -> small staging -> 3 CTAs/SM.
// ---------------------------------------------------------------------------
#define K1_A    0
#define K1_B    18432                  // 128*144
#define K1_STG  36864
#define K1_SMEM (36864 + 34816)        // 71680 B

__global__ __launch_bounds__(256, 3) void k1_wmma(const float* __restrict__ x)
{
    extern __shared__ char sm[];
    __half* Ah = (__half*)(sm + K1_A);
    __half* Bh = (__half*)(sm + K1_B);
    float*  Sg = (float*) (sm + K1_STG);
    const int tid = threadIdx.x;
    const int wid = tid >> 5, lid = tid & 31;
    const int p0  = blockIdx.x * 128;
    const int b   = p0 >> 14;
    const int pi  = p0 & 16383;

    for (int j = tid; j < 1024; j += 256) {
        int o = j >> 3, seg = j & 7;
        *(uint4*)((char*)Bh + o*144 + seg*16) = wB1h[j];
    }
    const float* xb = x + (size_t)b * 64 * HW + pi;
    for (int j = tid; j < 4096; j += 256) {
        int cp = j >> 7, p = j & 127;
        float va = xb[(2*cp  )*HW + p];
        float vb = xb[(2*cp+1)*HW + p];
        __half2 h = __floats2half2_rn(va, vb);
        *(uint32_t*)((char*)Ah + p*144 + cp*4) = *(uint32_t*)&h;
    }
    __syncthreads();

    // emit oct-packed x gather table
    for (int j = tid; j < 1024; j += 256) {
        int c8 = j >> 7, p = j & 127;
        uint4 v = *(uint4*)((char*)Ah + p*144 + c8*16);
        g_x8[(size_t)((b*8 + c8) << 14) + pi + p] = v;
    }

    float* st = Sg + wid*16*68;
    for (int half = 0; half < 2; half++) {
        wmma::fragment<wmma::accumulator, 16, 16, 16, float> acc[4];
#pragma unroll
        for (int n = 0; n < 4; n++) wmma::fill_fragment(acc[n], 0.f);
#pragma unroll
        for (int k = 0; k < 4; k++) {
            wmma::fragment<wmma::matrix_a, 16, 16, 16, __half, wmma::row_major> fa;
            wmma::load_matrix_sync(fa, Ah + wid*16*PADH + k*16, PADH);
#pragma unroll
            for (int n = 0; n < 4; n++) {
                wmma::fragment<wmma::matrix_b, 16, 16, 16, __half, wmma::col_major> fb;
                wmma::load_matrix_sync(fb, Bh + (half*4 + n)*16*PADH + k*16, PADH);
                wmma::mma_sync(acc[n], fa, fb, acc[n]);
            }
        }
#pragma unroll
        for (int n = 0; n < 4; n++)
            wmma::store_matrix_sync(st + n*16, acc[n], 68, wmma::mem_row_major);
        __syncwarp();
#pragma unroll
        for (int i = 0; i < 4; i++) {
            int item  = i*32 + lid;
            int row   = item >> 3;
            int chunk = item & 7;
            const float* s = st + row*68 + chunk*8;
            uint4 o4;
            __half2 h;
            h = __floats2half2_rn(s[0], s[1]); o4.x = *(uint32_t*)&h;
            h = __floats2half2_rn(s[2], s[3]); o4.y = *(uint32_t*)&h;
            h = __floats2half2_rn(s[4], s[5]); o4.z = *(uint32_t*)&h;
            h = __floats2half2_rn(s[6], s[7]); o4.w = *(uint32_t*)&h;
            int gp = p0 + wid*16 + row;
            if (half == 0) t1Th[(size_t)gp*8 + chunk] = o4;
            else           t2Th[(size_t)gp*8 + chunk] = o4;
        }
        __syncwarp();
    }
}

// ---------------------------------------------------------------------------
// Kernel 2: 3x3 convs, 2 output rows/block, 8 warps of 32px x 32couts.
// A: 4 dy-row sections, 130 px, 160B pixel stride (dx shift = 160B, 32B-aligned).
// B path0: tap-packed 18-row sections (2592B/tap) -- the N>=18 fragment
// columns read the next tap's rows; those couts are never stored.
// ---------------------------------------------------------------------------
#define K2_ASEC  20800                 // 130*160 bytes per dy section
#define K2_B     83200                 // 4*20800
#define K2_SMEM  (83200 + 25344)       // 108544 B -> 2 CTAs/SM

__global__ __launch_bounds__(256) void k2_wmma()
{
    extern __shared__ char sm[];
    __half* Ah = (__half*)sm;
    __half* Bh = (__half*)(sm + K2_B);
    float*  Sg = (float*)sm;             // overlay on A after MMA phase
    const int tid = threadIdx.x;
    const int wid = tid >> 5, lid = tid & 31;
    const int b  = blockIdx.x >> 6;
    const int y0 = (blockIdx.x & 63) * 2;
    const int path = blockIdx.y;

    if (path == 0) {
        // 9 taps x 18 cout rows x 8 segs (144B row stride, 2592B/tap)
        for (int j = tid; j < 1296; j += 256) {
            int t = j / 144, r = j - t*144;
            int o = r >> 3, seg = r & 7;
            *(uint4*)((char*)Bh + t*2592 + o*144 + seg*16) = wB2o[t*256 + o*8 + seg];
        }
    } else {
        // 9 taps x 16 cout rows x 8 segs (2304B/tap)
        for (int j = tid; j < 1152; j += 256) {
            int t = j >> 7, r = j & 127;
            int o = r >> 3, seg = r & 7;
            *(uint4*)((char*)Bh + t*2304 + o*144 + seg*16) = wB2m[t*256 + o*8 + seg];
        }
    }
    // A: 4 input rows (y0-1..y0+2), buffer px i = image px i-1, 160B stride
    const uint4* src = path ? t2Th : t1Th;
    const uint4 z4 = make_uint4(0u,0u,0u,0u);
    for (int j = tid; j < 4160; j += 256) {      // 4 rows * 130 px * 8 segs
        int d = j / 1040, r = j - d*1040;
        int p = r >> 3, seg = r & 7;
        int yy = y0 + d - 1;
        int px = p - 1;
        uint4 v = z4;
        if ((unsigned)yy < 128u && (unsigned)px < 128u)
            v = src[(size_t)((b << 14) + (yy << 7) + px) * 8 + seg];
        *(uint4*)((char*)Ah + d*K2_ASEC + p*160 + seg*16) = v;
    }
    __syncthreads();

    const int rl  = wid >> 2;            // local output row 0/1
    const int px0 = (wid & 3) * 32;      // warp's 32-pixel strip

    if (path == 0) {
        wmma::fragment<wmma::accumulator, 16, 16, 16, float> acc[2][2];
        wmma::fill_fragment(acc[0][0], 0.f);
        wmma::fill_fragment(acc[0][1], 0.f);
        wmma::fill_fragment(acc[1][0], 0.f);
        wmma::fill_fragment(acc[1][1], 0.f);
        for (int dy = 0; dy < 3; dy++) {
#pragma unroll
            for (int dx = 0; dx < 3; dx++) {
                const __half* Ad = Ah + (rl + dy)*(K2_ASEC/2) + (px0 + dx)*80;
                const __half* Bt = Bh + (dy*3 + dx)*1296;   // halfs: 2592B/tap
#pragma unroll
                for (int k = 0; k < 4; k++) {
                    wmma::fragment<wmma::matrix_a, 16, 16, 16, __half, wmma::row_major> fa0, fa1;
                    wmma::load_matrix_sync(fa0, Ad + k*16, 80);
                    wmma::load_matrix_sync(fa1, Ad + 16*80 + k*16, 80);
                    wmma::fragment<wmma::matrix_b, 16, 16, 16, __half, wmma::col_major> fb0, fb1;
                    wmma::load_matrix_sync(fb0, Bt + k*16, PADH);
                    wmma::load_matrix_sync(fb1, Bt + 16*PADH + k*16, PADH);
                    wmma::mma_sync(acc[0][0], fa0, fb0, acc[0][0]);
                    wmma::mma_sync(acc[0][1], fa0, fb1, acc[0][1]);
                    wmma::mma_sync(acc[1][0], fa1, fb0, acc[1][0]);
                    wmma::mma_sync(acc[1][1], fa1, fb1, acc[1][1]);
                }
            }
        }
        __syncthreads();   // A reads done before staging overlay
        float* st = Sg + (rl*128 + px0)*36;
        wmma::store_matrix_sync(st,            acc[0][0], 36, wmma::mem_row_major);
        wmma::store_matrix_sync(st + 16,       acc[0][1], 36, wmma::mem_row_major);
        wmma::store_matrix_sync(st + 16*36,    acc[1][0], 36, wmma::mem_row_major);
        wmma::store_matrix_sync(st + 16*36+16, acc[1][1], 36, wmma::mem_row_major);
        __syncwarp();
        const int p_ = lid & 15;
        const int oh = lid >> 4;
#pragma unroll
        for (int pa = 0; pa < 2; pa++) {
            const float* s = st + (pa*16 + p_)*36;
            int pix = (y0 + rl)*Wdim + px0 + pa*16 + p_;
#pragma unroll
            for (int j = 0; j < 9; j++) {
                int o = oh*9 + j;
                g_off[((size_t)b*18 + o)*HW + pix] = s[o];
            }
        }
    } else {
        wmma::fragment<wmma::accumulator, 16, 16, 16, float> acc[2];
        wmma::fill_fragment(acc[0], 0.f);
        wmma::fill_fragment(acc[1], 0.f);
        for (int dy = 0; dy < 3; dy++) {
#pragma unroll
            for (int dx = 0; dx < 3; dx++) {
                const __half* Ad = Ah + (rl + dy)*(K2_ASEC/2) + (px0 + dx)*80;
                const __half* Bt = Bh + (dy*3 + dx)*1152;   // halfs: 2304B/tap
#pragma unroll
                for (int k = 0; k < 4; k++) {
                    wmma::fragment<wmma::matrix_a, 16, 16, 16, __half, wmma::row_major> fa0, fa1;
                    wmma::load_matrix_sync(fa0, Ad + k*16, 80);
                    wmma::load_matrix_sync(fa1, Ad + 16*80 + k*16, 80);
                    wmma::fragment<wmma::matrix_b, 16, 16, 16, __half, wmma::col_major> fb;
                    wmma::load_matrix_sync(fb, Bt + k*16, PADH);
                    wmma::mma_sync(acc[0], fa0, fb, acc[0]);
                    wmma::mma_sync(acc[1], fa1, fb, acc[1]);
                }
            }
        }
        __syncthreads();
        float* st = Sg + (rl*128 + px0)*36;
        wmma::store_matrix_sync(st,         acc[0], 36, wmma::mem_row_major);
        wmma::store_matrix_sync(st + 16*36, acc[1], 36, wmma::mem_row_major);
        __syncwarp();
        const int p_ = lid & 15;
        const int oh = lid >> 4;
        if (oh == 0) {
#pragma unroll
            for (int pa = 0; pa < 2; pa++) {
                const float* s = st + (pa*16 + p_)*36;
                int pix = (y0 + rl)*Wdim + px0 + pa*16 + p_;
#pragma unroll
                for (int j = 0; j < 9; j++) {
                    float v = s[j];
                    g_mask[((size_t)b*9 + j)*HW + pix] = 1.f / (1.f + expf(-v));
                }
            }
        }
    }
}

// ---------------------------------------------------------------------------
// Kernel 3: deformable gather (8-channel LDG.128) + einsum + bias,
// fused groupnorm partials. (R8 formulation: 52 regs, 2 CTAs/SM.)
// ---------------------------------------------------------------------------
__global__ __launch_bounds__(512) void k3_sample(
    const float* __restrict__ wgt,
    const float* __restrict__ bias)
{
    __shared__ float4 sw8[9*8*2];       // [k][cg] weight oct (2x float4)
    __shared__ float  sb[64];
    __shared__ int4   sI[9*64];
    __shared__ float4 sC[9*64];

    const int tid = threadIdx.x;
    if (tid < 144) {
        int k = tid / 16, idx = tid & 15;
        int cg = idx >> 1, h = idx & 1;
        int c0 = cg*8 + h*4;
        sw8[(k*8 + cg)*2 + h] = make_float4(wgt[(c0  )*9 + k], wgt[(c0+1)*9 + k],
                                            wgt[(c0+2)*9 + k], wgt[(c0+3)*9 + k]);
    }
    if (tid >= 448) sb[tid - 448] = bias[tid - 448];

    const int blk = blockIdx.x;             // 1024
    const int b   = blk >> 8;
    const int p0  = (blk & 255) * 64;

    for (int e = tid; e < 576; e += 512) {
        const int k = e >> 6;
        const int p = e & 63;
        const int pix = p0 + p;
        const int gy = pix >> 7, gx = pix & 127;
        const float* offb = g_off  + (size_t)b * 18 * HW;
        const float* mkb  = g_mask + (size_t)b * 9  * HW;
        float oy = offb[(2*k  )*HW + pix];
        float ox = offb[(2*k+1)*HW + pix];
        float mk = mkb [ k     *HW + pix];
        float py  = oy + (float)gy + (float)(k/3 - 1);
        float pxx = ox + (float)gx + (float)(k%3 - 1);
        float y0f = floorf(py),  x0f = floorf(pxx);
        float wy1 = py - y0f,    wx1 = pxx - x0f;
        int   y0  = (int)y0f,    xx0 = (int)x0f;
        int cy0 = min(max(y0,   0), Hdim-1), cy1 = min(max(y0+1, 0), Hdim-1);
        int cx0 = min(max(xx0,  0), Wdim-1), cx1 = min(max(xx0+1,0), Wdim-1);
        float vy0 = (y0   >= 0 && y0   < Hdim) ? 1.f : 0.f;
        float vy1 = (y0+1 >= 0 && y0+1 < Hdim) ? 1.f : 0.f;
        float vx0 = (xx0  >= 0 && xx0  < Wdim) ? 1.f : 0.f;
        float vx1 = (xx0+1>= 0 && xx0+1< Wdim) ? 1.f : 0.f;
        float ay0 = (1.f - wy1) * vy0 * mk;
        float ay1 = wy1 * vy1 * mk;
        float ax0 = (1.f - wx1) * vx0;
        float ax1 = wx1 * vx1;
        sI[k*64 + p] = make_int4(cy0*Wdim + cx0, cx1 - cx0, (cy1 - cy0)*Wdim, 0);
        sC[k*64 + p] = make_float4(ay0*ax0, ay0*ax1, ay1*ax0, ay1*ax1);
    }
    __syncthreads();

    const int p   = tid & 63;
    const int cg  = tid >> 6;
    const int pix = p0 + p;
    const uint4* x8 = g_x8 + (size_t)((b*8 + cg) << 14);

    float a0=0.f,a1=0.f,a2=0.f,a3=0.f,a4=0.f,a5=0.f,a6=0.f,a7=0.f;
    for (int k = 0; k < 9; k++) {
        int4   I  = sI[k*64 + p];
        float4 C  = sC[k*64 + p];
        float4 Wa = sw8[(k*8 + cg)*2];
        float4 Wb = sw8[(k*8 + cg)*2 + 1];
        uint4 u00 = __ldg(x8 + I.x);
        uint4 u01 = __ldg(x8 + I.x + I.y);
        uint4 u10 = __ldg(x8 + I.x + I.z);
        uint4 u11 = __ldg(x8 + I.x + I.z + I.y);
        float2 f00, f01, f10, f11;
        float s;
        f00 = __half22float2(*(__half2*)&u00.x); f01 = __half22float2(*(__half2*)&u01.x);
        f10 = __half22float2(*(__half2*)&u10.x); f11 = __half22float2(*(__half2*)&u11.x);
        s = C.x*f00.x; s = fmaf(C.y,f01.x,s); s = fmaf(C.z,f10.x,s); s = fmaf(C.w,f11.x,s); a0 = fmaf(Wa.x, s, a0);
        s = C.x*f00.y; s = fmaf(C.y,f01.y,s); s = fmaf(C.z,f10.y,s); s = fmaf(C.w,f11.y,s); a1 = fmaf(Wa.y, s, a1);
        f00 = __half22float2(*(__half2*)&u00.y); f01 = __half22float2(*(__half2*)&u01.y);
        f10 = __half22float2(*(__half2*)&u10.y); f11 = __half22float2(*(__half2*)&u11.y);
        s = C.x*f00.x; s = fmaf(C.y,f01.x,s); s = fmaf(C.z,f10.x,s); s = fmaf(C.w,f11.x,s); a2 = fmaf(Wa.z, s, a2);
        s = C.x*f00.y; s = fmaf(C.y,f01.y,s); s = fmaf(C.z,f10.y,s); s = fmaf(C.w,f11.y,s); a3 = fmaf(Wa.w, s, a3);
        f00 = __half22float2(*(__half2*)&u00.z); f01 = __half22float2(*(__half2*)&u01.z);
        f10 = __half22float2(*(__half2*)&u10.z); f11 = __half22float2(*(__half2*)&u11.z);
        s = C.x*f00.x; s = fmaf(C.y,f01.x,s); s = fmaf(C.z,f10.x,s); s = fmaf(C.w,f11.x,s); a4 = fmaf(Wb.x, s, a4);
        s = C.x*f00.y; s = fmaf(C.y,f01.y,s); s = fmaf(C.z,f10.y,s); s = fmaf(C.w,f11.y,s); a5 = fmaf(Wb.y, s, a5);
        f00 = __half22float2(*(__half2*)&u00.w); f01 = __half22float2(*(__half2*)&u01.w);
        f10 = __half22float2(*(__half2*)&u10.w); f11 = __half22float2(*(__half2*)&u11.w);
        s = C.x*f00.x; s = fmaf(C.y,f01.x,s); s = fmaf(C.z,f10.x,s); s = fmaf(C.w,f11.x,s); a6 = fmaf(Wb.z, s, a6);
        s = C.x*f00.y; s = fmaf(C.y,f01.y,s); s = fmaf(C.z,f10.y,s); s = fmaf(C.w,f11.y,s); a7 = fmaf(Wb.w, s, a7);
    }

    const int c0 = cg*8;
    float v0 = a0 + sb[c0  ], v1 = a1 + sb[c0+1];
    float v2 = a2 + sb[c0+2], v3 = a3 + sb[c0+3];
    float v4 = a4 + sb[c0+4], v5 = a5 + sb[c0+5];
    float v6 = a6 + sb[c0+6], v7 = a7 + sb[c0+7];
    g_pre[((size_t)b*64 + c0    )*HW + pix] = v0;
    g_pre[((size_t)b*64 + c0 + 1)*HW + pix] = v1;
    g_pre[((size_t)b*64 + c0 + 2)*HW + pix] = v2;
    g_pre[((size_t)b*64 + c0 + 3)*HW + pix] = v3;
    g_pre[((size_t)b*64 + c0 + 4)*HW + pix] = v4;
    g_pre[((size_t)b*64 + c0 + 5)*HW + pix] = v5;
    g_pre[((size_t)b*64 + c0 + 6)*HW + pix] = v6;
    g_pre[((size_t)b*64 + c0 + 7)*HW + pix] = v7;
    float s0 = v0+v1, q0 = fmaf(v0,v0, v1*v1);
    float s1 = v2+v3, q1 = fmaf(v2,v2, v3*v3);
    float s2 = v4+v5, q2 = fmaf(v4,v4, v5*v5);
    float s3 = v6+v7, q3 = fmaf(v6,v6, v7*v7);
#pragma unroll
    for (int o = 16; o > 0; o >>= 1) {
        s0 += __shfl_xor_sync(0xFFFFFFFF, s0, o);
        q0 += __shfl_xor_sync(0xFFFFFFFF, q0, o);
        s1 += __shfl_xor_sync(0xFFFFFFFF, s1, o);
        q1 += __shfl_xor_sync(0xFFFFFFFF, q1, o);
        s2 += __shfl_xor_sync(0xFFFFFFFF, s2, o);
        q2 += __shfl_xor_sync(0xFFFFFFFF, q2, o);
        s3 += __shfl_xor_sync(0xFFFFFFFF, s3, o);
        q3 += __shfl_xor_sync(0xFFFFFFFF, q3, o);
    }
    if ((tid & 31) == 0) {
        int wslot = (tid >> 5) & 1;
        float2* dst = &g_part[((size_t)blk*2 + wslot)*32 + 4*cg];
        dst[0] = make_float2(s0, q0);
        dst[1] = make_float2(s1, q1);
        dst[2] = make_float2(s2, q2);
        dst[3] = make_float2(s3, q3);
    }
}

// ---------------------------------------------------------------------------
// Kernel 4a: final stats: reduce warp-partials per (b,group).
// ---------------------------------------------------------------------------
__global__ __launch_bounds__(256) void k4a_final()
{
    __shared__ float2 sp[256];
    const int bg = blockIdx.x;              // 0..127
    const int b = bg >> 5, g = bg & 31;
    float s = 0.f, q = 0.f;
    for (int j = threadIdx.x; j < 512; j += 256) {
        float2 v = g_part[(size_t)(b*512 + j)*32 + g];
        s += v.x; q += v.y;
    }
    sp[threadIdx.x] = make_float2(s, q);
    __syncthreads();
    for (int st = 128; st > 0; st >>= 1) {
        if (threadIdx.x < st) {
            sp[threadIdx.x].x += sp[threadIdx.x + st].x;
            sp[threadIdx.x].y += sp[threadIdx.x + st].y;
        }
        __syncthreads();
    }
    if (threadIdx.x == 0) {
        float mean = sp[0].x * (1.f/32768.f);
        float var  = sp[0].y * (1.f/32768.f) - mean*mean;
        g_stats[bg*2]   = mean;
        g_stats[bg*2+1] = rsqrtf(var + 1e-5f);
    }
}

// ---------------------------------------------------------------------------
// Kernel 4b: normalize + affine + exact GELU (float4)
// ---------------------------------------------------------------------------
__global__ __launch_bounds__(256) void k4b_norm(
    const float* __restrict__ gamma,
    const float* __restrict__ beta,
    float* __restrict__ out)
{
    const int i4 = blockIdx.x * 256 + threadIdx.x;
    const int i  = i4 << 2;
    const int c  = (i >> 14) & 63;
    const int b  = i >> 20;
    const int bg = b*32 + (c >> 1);
    const float mean = g_stats[bg*2];
    const float rstd = g_stats[bg*2 + 1];
    const float ga = __ldg(gamma + c), be = __ldg(beta + c);
    float4 v = ((const float4*)g_pre)[i4];
    float4 r;
    float yv;
    yv = (v.x - mean) * rstd * ga + be;
    r.x = 0.5f * yv * (1.f + erff(yv * 0.70710678118654752f));
    yv = (v.y - mean) * rstd * ga + be;
    r.y = 0.5f * yv * (1.f + erff(yv * 0.70710678118654752f));
    yv = (v.z - mean) * rstd * ga + be;
    r.z = 0.5f * yv * (1.f + erff(yv * 0.70710678118654752f));
    yv = (v.w - mean) * rstd * ga + be;
    r.w = 0.5f * yv * (1.f + erff(yv * 0.70710678118654752f));
    ((float4*)out)[i4] = r;
}

// ---------------------------------------------------------------------------
extern "C" void kernel_launch(void* const* d_in, const int* in_sizes, int n_in,
                              void* d_out, int out_size)
{
    const float* x       = (const float*)d_in[0];
    const float* w_off1  = (const float*)d_in[1];
    const float* w_off2  = (const float*)d_in[2];
    const float* w_mask1 = (const float*)d_in[3];
    const float* w_mask2 = (const float*)d_in[4];
    const float* weight  = (const float*)d_in[5];
    const float* bias    = (const float*)d_in[6];
    const float* gamma   = (const float*)d_in[7];
    const float* beta    = (const float*)d_in[8];
    float* out = (float*)d_out;

    cudaFuncSetAttribute(k1_wmma, cudaFuncAttributeMaxDynamicSharedMemorySize, K1_SMEM);
    cudaFuncSetAttribute(k2_wmma, cudaFuncAttributeMaxDynamicSharedMemorySize, K2_SMEM);

    k0_prep <<<64, 256>>>(w_off1, w_mask1, w_off2, w_mask2);
    k1_wmma <<<512, 256, K1_SMEM>>>(x);
    k2_wmma <<<dim3(256, 2), 256, K2_SMEM>>>();
    k3_sample<<<1024, 512>>>(weight, bias);
    k4a_final<<<128, 256>>>();
    k4b_norm<<<4096, 256>>>(gamma, beta, out);
}